// round 13
// baseline (speedup 1.0000x reference)
#include <cuda_runtime.h>
#include <math_constants.h>
#include <cstdint>

#define NN  131072      // nodes = B*S
#define HH  128         // hidden
#define EE  1048576     // edges
#define BB  2048        // molecules
#define SS  64          // nodes per molecule
#define NF  74          // input node features
#define DFF 512         // ffn hidden
#define LG  4           // gine layers
#define LSS 2           // sab layers
#define NH  8           // heads
#define DH  16          // head dim
#define NT  256         // gine threads per CTA
#define NTS 512         // sab threads per CTA
#define EPM 1024        // edge slots per molecule
#define RS  136         // padded row stride (floats) for 64x128 smem tiles
#define RS4 34          // float4s per padded row
#define WRS 264         // padded row stride for hi|lo weight chunks (8 mod 32)

typedef unsigned long long ull;

#define PACK2(out, a)  asm("mov.b64 %0, {%1, %1};" : "=l"(out) : "r"(__float_as_uint(a)))
#define FFMA2(acc, a, b) asm("fma.rn.f32x2 %0, %1, %2, %0;" : "+l"(acc) : "l"(a), "l"(b))
#define UNPK2(lo, hi, in) do { unsigned _l, _h; \
    asm("mov.b64 {%0, %1}, %2;" : "=r"(_l), "=r"(_h) : "l"(in)); \
    lo = __uint_as_float(_l); hi = __uint_as_float(_h); } while (0)

#define CP_ASYNC16(s, g) asm volatile("cp.async.cg.shared.global [%0], [%1], 16;" \
    :: "r"(s), "l"(g))
#define CP_COMMIT() asm volatile("cp.async.commit_group;" ::: "memory")
#define CP_WAIT0() asm volatile("cp.async.wait_group 0;" ::: "memory")
#define CP_WAIT1() asm volatile("cp.async.wait_group 1;" ::: "memory")

#define TF32(o, f_) asm("cvt.rna.tf32.f32 %0, %1;" : "=r"(o) : "f"(f_))
#define MMA_TF32(d, a, b0_, b1_) \
    asm volatile("mma.sync.aligned.m16n8k8.row.col.f32.tf32.tf32.f32 " \
        "{%0,%1,%2,%3},{%4,%5,%6,%7},{%8,%9},{%0,%1,%2,%3};" \
        : "+f"(d[0]), "+f"(d[1]), "+f"(d[2]), "+f"(d[3]) \
        : "r"(a[0]), "r"(a[1]), "r"(a[2]), "r"(a[3]), "r"(b0_), "r"(b1_))

// ---------------- scratch (device globals) -----------------------------------
__device__ __align__(16) float g_h[NN * HH];
__device__ __align__(16) float g_z[NN * HH];
__device__ __align__(16) float g_sum[HH];
__device__ __align__(16) float g_sumsq[HH];
__device__ __align__(16) float g_bn_a[HH];
__device__ __align__(16) float g_bn_c[HH];
__device__ int g_dcnt[NN];
__device__ int g_dfill[NN];
__device__ int g_dstart[BB * 65];
__device__ __align__(16) float4 g_efs[BB * EPM];
__device__ unsigned char g_srcs[BB * EPM];
// pre-split weights: 32 slices, each 128 rows x (128 hi | 128 lo)
__device__ __align__(16) float g_whl[32 * 128 * 256];

// ---------------- weight chunk streaming -------------------------------------
// cp.async a 16-row x 256-col (hi|lo) chunk into padded-stride smem
__device__ __forceinline__ void cp_whl(const float* __restrict__ g, float* __restrict__ s)
{
    unsigned sa = (unsigned)__cvta_generic_to_shared(s);
    for (int u = threadIdx.x; u < 1024; u += blockDim.x) {
        int row = u >> 6;       // 0..15
        int c4 = u & 63;        // 0..63
        CP_ASYNC16(sa + (row * (WRS / 4) + c4) * 16, g + row * 256 + c4 * 4);
    }
}

// plain fp32 W chunk (for sgemm_var / input projection)
__device__ __forceinline__ void cp_chunk_rows(const float* __restrict__ g, int gstride,
                                              float* __restrict__ s, int rows)
{
    unsigned sa = (unsigned)__cvta_generic_to_shared(s);
    int lim = rows * 32;
    for (int u = threadIdx.x; u < lim; u += blockDim.x) {
        int row = u >> 5;
        int col4 = u & 31;
        CP_ASYNC16(sa + (row * RS4 + col4) * 16, g + row * gstride + col4 * 4);
    }
}

// ---------------- tensor-core GEMM (3xTF32, pre-split W) ---------------------
// NW = warps in CTA (8 or 16). Each warp: 16-row group x (128/(NW/4))-col slab.
// C[64][RS] = act((accum? C : 0) + A[64][128] @ W + bias)
template<int NW>
__device__ __forceinline__ void sgemm64hl(const float* __restrict__ A,
                                          const float* __restrict__ Whl,
                                          const float* __restrict__ bias,
                                          float* __restrict__ C,
                                          float* __restrict__ wbuf,
                                          bool relu, bool accum)
{
    constexpr int JT = (NW == 8) ? 8 : 4;        // 8-col tiles per warp
    constexpr int CW = JT * 8;                   // col-slab width
    int tid = threadIdx.x;
    int w = tid >> 5;
    int lane = tid & 31;
    int g = lane >> 2;
    int tig = lane & 3;
    int ra = (w & 3) * 16 + g;
    int colBase = (w >> 2) * CW;

    float acc[JT][4];
#pragma unroll
    for (int j = 0; j < JT; j++)
#pragma unroll
        for (int q = 0; q < 4; q++) acc[j][q] = 0.0f;

    cp_whl(Whl, wbuf);
    CP_COMMIT();
#pragma unroll
    for (int c = 0; c < 8; c++) {
        if (c < 7) {
            cp_whl(Whl + (c + 1) * 16 * 256, wbuf + ((c + 1) & 1) * 16 * WRS);
            CP_COMMIT();
            CP_WAIT1();
        } else {
            CP_WAIT0();
        }
        __syncthreads();
        const float* Wc = wbuf + (c & 1) * 16 * WRS;
#pragma unroll
        for (int ks = 0; ks < 2; ks++) {
            int klo = ks * 8;
            const float* Ar = A + ra * RS + c * 16 + klo + tig;
            float a0f = Ar[0];
            float a2f = Ar[4];
            float a1f = Ar[8 * RS];
            float a3f = Ar[8 * RS + 4];
            unsigned ah[4], al[4];
            TF32(ah[0], a0f); TF32(ah[1], a1f); TF32(ah[2], a2f); TF32(ah[3], a3f);
            float r0 = a0f - __uint_as_float(ah[0]);
            float r1 = a1f - __uint_as_float(ah[1]);
            float r2 = a2f - __uint_as_float(ah[2]);
            float r3 = a3f - __uint_as_float(ah[3]);
            TF32(al[0], r0); TF32(al[1], r1); TF32(al[2], r2); TF32(al[3], r3);
            const float* Wh0 = Wc + (klo + tig) * WRS;
            const float* Wh1 = Wc + (klo + tig + 4) * WRS;
#pragma unroll
            for (int j = 0; j < JT; j++) {
                int n0 = colBase + j * 8 + g;
                unsigned bh0 = __float_as_uint(Wh0[n0]);
                unsigned bh1 = __float_as_uint(Wh1[n0]);
                unsigned bl0 = __float_as_uint(Wh0[128 + n0]);
                unsigned bl1 = __float_as_uint(Wh1[128 + n0]);
                MMA_TF32(acc[j], ah, bh0, bh1);   // hi*hi
                MMA_TF32(acc[j], ah, bl0, bl1);   // hi*lo
                MMA_TF32(acc[j], al, bh0, bh1);   // lo*hi
            }
        }
        __syncthreads();
    }
#pragma unroll
    for (int j = 0; j < JT; j++) {
        int cc = colBase + j * 8 + 2 * tig;
        float v0 = acc[j][0], v1 = acc[j][1], v2 = acc[j][2], v3 = acc[j][3];
        if (bias) {
            float bA = bias[cc], bB = bias[cc + 1];
            v0 += bA; v1 += bB; v2 += bA; v3 += bB;
        }
        if (relu) {
            v0 = fmaxf(v0, 0.f); v1 = fmaxf(v1, 0.f);
            v2 = fmaxf(v2, 0.f); v3 = fmaxf(v3, 0.f);
        }
        if (accum) {
            v0 += C[ra * RS + cc];
            v1 += C[ra * RS + cc + 1];
            v2 += C[(ra + 8) * RS + cc];
            v3 += C[(ra + 8) * RS + cc + 1];
        }
        C[ra * RS + cc]           = v0;
        C[ra * RS + cc + 1]       = v1;
        C[(ra + 8) * RS + cc]     = v2;
        C[(ra + 8) * RS + cc + 1] = v3;
    }
}

// ---------------- SIMT variable-K GEMM (input projection, K=74) --------------
#define GEMM_K4(ap0_, ap1_, ap2_, ap3_, Wrow_, accv_) do { \
    ulonglong2 w01_ = *reinterpret_cast<const ulonglong2*>(Wrow_); \
    ulonglong2 w23_ = *reinterpret_cast<const ulonglong2*>((Wrow_) + 4); \
    FFMA2(accv_[0][0], ap0_, w01_.x); FFMA2(accv_[0][1], ap0_, w01_.y); \
    FFMA2(accv_[0][2], ap0_, w23_.x); FFMA2(accv_[0][3], ap0_, w23_.y); \
    FFMA2(accv_[1][0], ap1_, w01_.x); FFMA2(accv_[1][1], ap1_, w01_.y); \
    FFMA2(accv_[1][2], ap1_, w23_.x); FFMA2(accv_[1][3], ap1_, w23_.y); \
    FFMA2(accv_[2][0], ap2_, w01_.x); FFMA2(accv_[2][1], ap2_, w01_.y); \
    FFMA2(accv_[2][2], ap2_, w23_.x); FFMA2(accv_[2][3], ap2_, w23_.y); \
    FFMA2(accv_[3][0], ap3_, w01_.x); FFMA2(accv_[3][1], ap3_, w01_.y); \
    FFMA2(accv_[3][2], ap3_, w23_.x); FFMA2(accv_[3][3], ap3_, w23_.y); \
} while (0)

__device__ __forceinline__ void sgemm_var(const float* __restrict__ A, int lda, int K,
                                          const float* __restrict__ Wg, int gstride,
                                          const float* __restrict__ bias,
                                          float* __restrict__ C,
                                          float* __restrict__ wbuf)
{
    int tid = threadIdx.x;
    int r0 = (tid >> 4) * 4;
    int c0 = (tid & 15) * 8;
    ull acc[4][4];
#pragma unroll
    for (int i = 0; i < 4; i++)
#pragma unroll
        for (int j = 0; j < 4; j++) acc[i][j] = 0ULL;

    int nch = (K + 31) / 32;
    cp_chunk_rows(Wg, gstride, wbuf, K < 32 ? K : 32);
    CP_COMMIT();
    for (int c = 0; c < nch; c++) {
        if (c + 1 < nch) {
            int rows = K - (c + 1) * 32;
            if (rows > 32) rows = 32;
            cp_chunk_rows(Wg + (c + 1) * 32 * gstride, gstride,
                          wbuf + ((c + 1) & 1) * 32 * RS, rows);
            CP_COMMIT();
            CP_WAIT1();
        } else {
            CP_WAIT0();
        }
        __syncthreads();
        const float* Wc = wbuf + (c & 1) * 32 * RS;
        int kbase = c * 32;
        int kn = K - kbase;
        if (kn > 32) kn = 32;
        for (int kk = 0; kk < kn; kk++) {
            ull p0, p1, p2, p3;
            float v0 = A[(r0 + 0) * lda + kbase + kk];
            float v1 = A[(r0 + 1) * lda + kbase + kk];
            float v2 = A[(r0 + 2) * lda + kbase + kk];
            float v3 = A[(r0 + 3) * lda + kbase + kk];
            PACK2(p0, v0); PACK2(p1, v1); PACK2(p2, v2); PACK2(p3, v3);
            GEMM_K4(p0, p1, p2, p3, &Wc[kk * RS + c0], acc);
        }
        __syncthreads();
    }
#pragma unroll
    for (int i = 0; i < 4; i++)
#pragma unroll
        for (int j = 0; j < 4; j++) {
            float lo, hi;
            UNPK2(lo, hi, acc[i][j]);
            lo += bias[c0 + 2 * j];
            hi += bias[c0 + 2 * j + 1];
            C[(r0 + i) * RS + c0 + 2 * j]     = lo;
            C[(r0 + i) * RS + c0 + 2 * j + 1] = hi;
        }
}

// per-row layernorm over 64 rows; X,O stride RS; works for any warp count
__device__ __forceinline__ void ln_rows(const float* __restrict__ X, float* __restrict__ O,
                                        const float* __restrict__ gg, const float* __restrict__ bb)
{
    int nw = blockDim.x >> 5;
    int wid = threadIdx.x >> 5;
    int lane = threadIdx.x & 31;
    for (int r = wid; r < SS; r += nw) {
        float v0 = X[r * RS + lane];
        float v1 = X[r * RS + lane + 32];
        float v2 = X[r * RS + lane + 64];
        float v3 = X[r * RS + lane + 96];
        float s = v0 + v1 + v2 + v3;
        float ss = v0 * v0 + v1 * v1 + v2 * v2 + v3 * v3;
#pragma unroll
        for (int o = 16; o; o >>= 1) {
            s += __shfl_xor_sync(0xffffffffu, s, o);
            ss += __shfl_xor_sync(0xffffffffu, ss, o);
        }
        float mu = s * (1.0f / HH);
        float var = ss * (1.0f / HH) - mu * mu;
        float inv = rsqrtf(var + 1e-5f);
        O[r * RS + lane]      = (v0 - mu) * inv * gg[lane]      + bb[lane];
        O[r * RS + lane + 32] = (v1 - mu) * inv * gg[lane + 32] + bb[lane + 32];
        O[r * RS + lane + 64] = (v2 - mu) * inv * gg[lane + 64] + bb[lane + 64];
        O[r * RS + lane + 96] = (v3 - mu) * inv * gg[lane + 96] + bb[lane + 96];
    }
}

// ---------------- prologue: edge hist + weight hi/lo split (fused) -----------
__global__ void edge_hist_whl_kernel(const int* __restrict__ dst,
                                     const float* __restrict__ gW1,
                                     const float* __restrict__ gW2,
                                     const float* __restrict__ Wq,
                                     const float* __restrict__ Wk,
                                     const float* __restrict__ Wv,
                                     const float* __restrict__ Wo,
                                     const float* __restrict__ fW1,
                                     const float* __restrict__ fW2)
{
    int b = blockIdx.x;
    if (b < EE / 256) {
        int e = b * 256 + threadIdx.x;
        atomicAdd(&g_dcnt[dst[e]], 1);      // g_dcnt zero at entry (invariant)
        return;
    }
    int sb = b - EE / 256;
    int s = sb >> 6;
    int i = (sb & 63) * 256 + threadIdx.x;
    int k = i >> 7;
    int j = i & 127;
    const float* srcp;
    if (s < 4) {
        srcp = gW1 + s * 16384 + k * 128 + j;
    } else if (s < 8) {
        srcp = gW2 + (s - 4) * 16384 + k * 128 + j;
    } else {
        int l = (s - 8) / 12;
        int t = (s - 8) % 12;
        if (t < 4) {
            const float* base = (t == 0) ? Wq : (t == 1) ? Wk : (t == 2) ? Wv : Wo;
            srcp = base + l * 16384 + k * 128 + j;
        } else if (t < 8) {
            int c = t - 4;
            srcp = fW1 + l * 65536 + k * 512 + c * 128 + j;
        } else {
            int c = t - 8;
            srcp = fW2 + l * 65536 + (c * 128 + k) * 128 + j;
        }
    }
    float v = *srcp;
    unsigned hi;
    TF32(hi, v);
    float lo = v - __uint_as_float(hi);
    unsigned lou;
    TF32(lou, lo);
    float* dstp = g_whl + s * 32768 + k * 256;
    dstp[j] = __uint_as_float(hi);
    dstp[128 + j] = __uint_as_float(lou);
}

__global__ void dscan_kernel()
{
    __shared__ int sh[64];
    int m = blockIdx.x;
    int t = threadIdx.x;
    int c = g_dcnt[m * 64 + t];
    sh[t] = c;
    __syncthreads();
    for (int off = 1; off < 64; off <<= 1) {
        int v = (t >= off) ? sh[t - off] : 0;
        __syncthreads();
        sh[t] += v;
        __syncthreads();
    }
    g_dstart[m * 65 + t] = sh[t] - c;
    if (t == 63) g_dstart[m * 65 + 64] = sh[63];
    g_dcnt[m * 64 + t] = 0;
    g_dfill[m * 64 + t] = 0;
}

__global__ void edge_scatter_gather_kernel(const int* __restrict__ dst,
                                           const int* __restrict__ src,
                                           const float* __restrict__ ef)
{
    int e = blockIdx.x * blockDim.x + threadIdx.x;
    if (e < EE) {
        int dv = dst[e];
        int p = atomicAdd(&g_dfill[dv], 1);
        int m = dv >> 6;
        int d = dv & 63;
        int slot = m * EPM + g_dstart[m * 65 + d] + p;
        g_efs[slot] = reinterpret_cast<const float4*>(ef)[e];
        g_srcs[slot] = (unsigned char)(src[e] & (SS - 1));
    }
}

// ---------------- GINE layer (1 molecule per CTA, 2 CTAs/SM) -----------------
__global__ void __launch_bounds__(NT, 2) gine_kernel(
                            const float* __restrict__ nf,
                            const float* __restrict__ Win, const float* __restrict__ bin,
                            const float* __restrict__ We, const float* __restrict__ be,
                            int s1, const float* __restrict__ b1,
                            int s2, const float* __restrict__ b2,
                            int mode)
{
    extern __shared__ float smem[];
    float* hb   = smem;                  // 64xRS (h; later reused as z1)
    float* ag   = hb + SS * RS;          // 64xRS (nf / z -> z2)
    float* wbuf = ag + SS * RS;          // 2x32xRS floats
    float* wesm = wbuf + 2 * 32 * RS;    // 4x128
    float* besm = wesm + 4 * HH;         // 128
    int m = blockIdx.x;
    int row0 = m * SS;
    int tid = threadIdx.x;
    const float* W1hl = g_whl + (size_t)s1 * 32768;
    const float* W2hl = g_whl + (size_t)s2 * 32768;

    {
        for (int i = tid; i < 4 * HH; i += NT) wesm[i] = We[i];
        if (tid < HH) besm[tid] = be[tid];
    }
    if (mode == 0) {
        for (int i = tid; i < SS * NF; i += NT) ag[i] = nf[row0 * NF + i];
        sgemm_var(ag, NF, NF, Win, HH, bin, hb, wbuf);
        __syncthreads();
        {
            float4* gh4 = reinterpret_cast<float4*>(g_h + row0 * HH);
            for (int i = tid; i < SS * 32; i += NT) {
                int r = i >> 5, c4 = i & 31;
                gh4[r * 32 + c4] = *reinterpret_cast<const float4*>(&hb[r * RS + c4 * 4]);
            }
        }
    } else {
        float4* gh4 = reinterpret_cast<float4*>(g_h + row0 * HH);
        const float4* gz4 = reinterpret_cast<const float4*>(g_z + row0 * HH);
        for (int i = tid; i < SS * 32; i += NT) {
            int rr = i >> 5, c4 = i & 31;
            int f0 = c4 * 4;
            float4 a = *reinterpret_cast<const float4*>(&g_bn_a[f0]);
            float4 c = *reinterpret_cast<const float4*>(&g_bn_c[f0]);
            float4 z = gz4[i];
            float4 h = gh4[i];
            float4 r;
            r.x = fmaxf(fmaf(z.x, a.x, c.x), 0.f) + h.x;
            r.y = fmaxf(fmaf(z.y, a.y, c.y), 0.f) + h.y;
            r.z = fmaxf(fmaf(z.z, a.z, c.z), 0.f) + h.z;
            r.w = fmaxf(fmaf(z.w, a.w, c.w), 0.f) + h.w;
            *reinterpret_cast<float4*>(&hb[rr * RS + c4 * 4]) = r;
            gh4[i] = r;
        }
    }
    __syncthreads();

    // message passing: 8 warps over 64 dst rows, atomic-free
    {
        int wid = tid >> 5, lane = tid & 31;
        int ebeg = m * EPM;
        const int* gd = g_dstart + m * 65;
        float wr[4][4], br[4];
#pragma unroll
        for (int q = 0; q < 4; q++) {
            int f = lane + 32 * q;
            wr[q][0] = wesm[f];
            wr[q][1] = wesm[HH + f];
            wr[q][2] = wesm[2 * HH + f];
            wr[q][3] = wesm[3 * HH + f];
            br[q] = besm[f];
        }
        for (int d = wid; d < SS; d += 8) {
            float a0 = 0.f, a1 = 0.f, a2 = 0.f, a3 = 0.f;
            int b = gd[d], en = gd[d + 1];
            for (int idx = b; idx < en; idx++) {
                float4 f4 = g_efs[ebeg + idx];
                int s = g_srcs[ebeg + idx];
                const float* hr = &hb[s * RS];
                float m0 = hr[lane]      + f4.x * wr[0][0] + f4.y * wr[0][1] + f4.z * wr[0][2] + f4.w * wr[0][3] + br[0];
                float m1 = hr[lane + 32] + f4.x * wr[1][0] + f4.y * wr[1][1] + f4.z * wr[1][2] + f4.w * wr[1][3] + br[1];
                float m2_ = hr[lane + 64] + f4.x * wr[2][0] + f4.y * wr[2][1] + f4.z * wr[2][2] + f4.w * wr[2][3] + br[2];
                float m3 = hr[lane + 96] + f4.x * wr[3][0] + f4.y * wr[3][1] + f4.z * wr[3][2] + f4.w * wr[3][3] + br[3];
                a0 += fmaxf(m0, 0.f);
                a1 += fmaxf(m1, 0.f);
                a2 += fmaxf(m2_, 0.f);
                a3 += fmaxf(m3, 0.f);
            }
            ag[d * RS + lane]      = a0 + hb[d * RS + lane];
            ag[d * RS + lane + 32] = a1 + hb[d * RS + lane + 32];
            ag[d * RS + lane + 64] = a2 + hb[d * RS + lane + 64];
            ag[d * RS + lane + 96] = a3 + hb[d * RS + lane + 96];
        }
    }
    sgemm64hl<8>(ag, W1hl, b1, hb, wbuf, true, false);    // z1 = relu(z@W1+b1)
    __syncthreads();
    sgemm64hl<8>(hb, W2hl, b2, ag, wbuf, false, false);   // z2 = z1@W2+b2
    __syncthreads();

    {   // BN partial stats
        int f = tid & 127;
        int c = tid >> 7;
        float s = 0.f, ss = 0.f;
        for (int r = c * 32; r < c * 32 + 32; r++) {
            float v = ag[r * RS + f];
            s += v;
            ss += v * v;
        }
        atomicAdd(&g_sum[f], s);
        atomicAdd(&g_sumsq[f], ss);
    }
    {
        float4* gz4 = reinterpret_cast<float4*>(g_z + row0 * HH);
        for (int i = tid; i < SS * 32; i += NT) {
            int r = i >> 5, c4 = i & 31;
            gz4[r * 32 + c4] = *reinterpret_cast<const float4*>(&ag[r * RS + c4 * 4]);
        }
    }
}

__global__ void bn_finalize_kernel(const float* __restrict__ bng, const float* __restrict__ bnb)
{
    int f = threadIdx.x;
    float mu = g_sum[f] * (1.0f / NN);
    float var = g_sumsq[f] * (1.0f / NN) - mu * mu;
    float inv = rsqrtf(var + 1e-5f);
    float a = inv * bng[f];
    g_bn_a[f] = a;
    g_bn_c[f] = bnb[f] - mu * a;
    g_sum[f] = 0.0f;
    g_sumsq[f] = 0.0f;
}

// ---------------- SAB layer (NTS=512, dual-head attention) -------------------
__global__ void __launch_bounds__(NTS) sab_kernel(
                           int sbase,
                           const float* __restrict__ b1, const float* __restrict__ b2,
                           const float* __restrict__ l1g, const float* __restrict__ l1b,
                           const float* __restrict__ l2g, const float* __restrict__ l2b,
                           const int* __restrict__ lengths, float* __restrict__ out,
                           int fuse_bn)
{
    extern __shared__ float smem[];
    float* xb   = smem;                  // 64xRS
    float* qb   = xb + SS * RS;
    float* kb   = qb + SS * RS;
    float* vb   = kb + SS * RS;
    float* wbuf = vb + SS * RS;          // 2x32xRS floats; aliased as 2x(64x65) scores
    int m = blockIdx.x;
    int row0 = m * SS;
    int tid = threadIdx.x;
    const float* Qhl = g_whl + (size_t)(sbase + 0) * 32768;
    const float* Khl = g_whl + (size_t)(sbase + 1) * 32768;
    const float* Vhl = g_whl + (size_t)(sbase + 2) * 32768;
    const float* Ohl = g_whl + (size_t)(sbase + 3) * 32768;

    {
        const float4* gx4 = reinterpret_cast<const float4*>(g_h + row0 * HH);
        if (fuse_bn) {
            const float4* gz4 = reinterpret_cast<const float4*>(g_z + row0 * HH);
            for (int i = tid; i < SS * 32; i += NTS) {
                int rr = i >> 5, c4 = i & 31;
                int f0 = c4 * 4;
                float4 a = *reinterpret_cast<const float4*>(&g_bn_a[f0]);
                float4 c = *reinterpret_cast<const float4*>(&g_bn_c[f0]);
                float4 z = gz4[i];
                float4 h = gx4[i];
                float4 r;
                r.x = fmaxf(fmaf(z.x, a.x, c.x), 0.f) + h.x;
                r.y = fmaxf(fmaf(z.y, a.y, c.y), 0.f) + h.y;
                r.z = fmaxf(fmaf(z.z, a.z, c.z), 0.f) + h.z;
                r.w = fmaxf(fmaf(z.w, a.w, c.w), 0.f) + h.w;
                *reinterpret_cast<float4*>(&xb[rr * RS + c4 * 4]) = r;
            }
        } else {
            for (int i = tid; i < SS * 32; i += NTS) {
                int rr = i >> 5, c4 = i & 31;
                *reinterpret_cast<float4*>(&xb[rr * RS + c4 * 4]) = gx4[i];
            }
        }
    }
    __syncthreads();
    ln_rows(xb, vb, l1g, l1b);                 // xn -> vb (temp)
    sgemm64hl<16>(vb, Qhl, nullptr, qb, wbuf, false, false);   // q = xn @ Wq
    sgemm64hl<16>(xb, Khl, nullptr, kb, wbuf, false, false);   // k = x @ Wk
    sgemm64hl<16>(xb, Vhl, nullptr, vb, wbuf, false, false);   // v = x @ Wv
    __syncthreads();

    int len = lengths[m];
    const float scale = 0.25f;
    for (int hp = 0; hp < NH / 2; hp++) {       // 2 heads per iteration
        int slot = tid >> 8;                    // 0/1
        int hh = hp * 2 + slot;
        float* scr = wbuf + slot * (SS * 65);
        int t = tid & 255;
        {   // scores
            int i = t >> 2;
            int j0 = (t & 3) * 16;
            ull q2[8];
            const ull* qrow = reinterpret_cast<const ull*>(&qb[i * RS + hh * DH]);
#pragma unroll
            for (int d2 = 0; d2 < 8; d2++) q2[d2] = qrow[d2];
#pragma unroll
            for (int jj = 0; jj < 16; jj++) {
                int j = j0 + jj;
                const ull* krow = reinterpret_cast<const ull*>(&kb[j * RS + hh * DH]);
                ull s2 = 0ULL;
#pragma unroll
                for (int d2 = 0; d2 < 8; d2++) FFMA2(s2, q2[d2], krow[d2]);
                float lo, hi;
                UNPK2(lo, hi, s2);
                float sdot = lo + hi;
                scr[i * 65 + j] = (i < len && j < len) ? sdot * scale : -CUDART_INF_F;
            }
        }
        __syncthreads();
        {   // softmax: warps 0-7 slot0, 8-15 slot1
            int wid = tid >> 5, lane = tid & 31;
            float* scr2 = wbuf + (wid >> 3) * (SS * 65);
            int w8 = wid & 7;
            for (int r = w8; r < SS; r += 8) {
                float x0 = scr2[r * 65 + lane];
                float x1 = scr2[r * 65 + lane + 32];
                float mx = fmaxf(x0, x1);
#pragma unroll
                for (int o = 16; o; o >>= 1) mx = fmaxf(mx, __shfl_xor_sync(0xffffffffu, mx, o));
                float e0 = (r < len && lane < len)      ? __expf(x0 - mx) : 0.f;
                float e1 = (r < len && lane + 32 < len) ? __expf(x1 - mx) : 0.f;
                float sm = e0 + e1;
#pragma unroll
                for (int o = 16; o; o >>= 1) sm += __shfl_xor_sync(0xffffffffu, sm, o);
                float rinv = (sm > 0.f) ? (1.0f / sm) : 0.f;
                scr2[r * 65 + lane]      = e0 * rinv;
                scr2[r * 65 + lane + 32] = e1 * rinv;
            }
        }
        __syncthreads();
        {   // att_h = alpha @ v_h, overwrite dead q_h columns
            int i2 = t >> 2;
            int d0 = (t & 3) * 4;
            ull acc0 = 0ULL, acc1 = 0ULL;
#pragma unroll 8
            for (int j = 0; j < SS; j++) {
                float al = scr[i2 * 65 + j];
                ull al2;
                PACK2(al2, al);
                const ull* vr = reinterpret_cast<const ull*>(&vb[j * RS + hh * DH + d0]);
                FFMA2(acc0, al2, vr[0]);
                FFMA2(acc1, al2, vr[1]);
            }
            float* qr = &qb[i2 * RS + hh * DH + d0];
            float lo, hi;
            UNPK2(lo, hi, acc0); qr[0] = lo; qr[1] = hi;
            UNPK2(lo, hi, acc1); qr[2] = lo; qr[3] = hi;
        }
        __syncthreads();
    }

    sgemm64hl<16>(qb, Ohl, nullptr, xb, wbuf, false, true);    // x += att @ Wo
    __syncthreads();
    ln_rows(xb, kb, l2g, l2b);                                 // xn2 -> kb
    for (int c = 0; c < 4; c++) {
        const float* F1hl = g_whl + (size_t)(sbase + 4 + c) * 32768;
        const float* F2hl = g_whl + (size_t)(sbase + 8 + c) * 32768;
        sgemm64hl<16>(kb, F1hl, b1 + c * HH, qb, wbuf, true, false);
        sgemm64hl<16>(qb, F2hl, (c == 0) ? b2 : nullptr, xb, wbuf, false, true);
    }
    __syncthreads();

    float* op = out ? out : g_h;
    {
        float4* o4 = reinterpret_cast<float4*>(op + row0 * HH);
        for (int i = tid; i < SS * 32; i += NTS) {
            int r = i >> 5, c4 = i & 31;
            o4[r * 32 + c4] = *reinterpret_cast<const float4*>(&xb[r * RS + c4 * 4]);
        }
    }
}

// ---------------- launch ------------------------------------------------------
extern "C" void kernel_launch(void* const* d_in, const int* in_sizes, int n_in,
                              void* d_out, int out_size)
{
    const float* node_feat = (const float*)d_in[0];
    const float* edge_feat = (const float*)d_in[1];
    const float* W_in   = (const float*)d_in[2];
    const float* b_in   = (const float*)d_in[3];
    const float* W_e    = (const float*)d_in[4];
    const float* b_e    = (const float*)d_in[5];
    const float* gW1    = (const float*)d_in[6];
    const float* gb1    = (const float*)d_in[7];
    const float* gW2    = (const float*)d_in[8];
    const float* gb2    = (const float*)d_in[9];
    const float* bn_g   = (const float*)d_in[10];
    const float* bn_b   = (const float*)d_in[11];
    const float* Wq     = (const float*)d_in[12];
    const float* Wk     = (const float*)d_in[13];
    const float* Wv     = (const float*)d_in[14];
    const float* Wo     = (const float*)d_in[15];
    const float* fW1    = (const float*)d_in[16];
    const float* fb1    = (const float*)d_in[17];
    const float* fW2    = (const float*)d_in[18];
    const float* fb2    = (const float*)d_in[19];
    const float* l1g    = (const float*)d_in[20];
    const float* l1b    = (const float*)d_in[21];
    const float* l2g    = (const float*)d_in[22];
    const float* l2b    = (const float*)d_in[23];
    const int*   src    = (const int*)d_in[24];
    const int*   dst    = (const int*)d_in[25];
    const int*   lengths= (const int*)d_in[26];

    const int GINE_SMEM = (2 * SS * RS + 2 * 32 * RS + 4 * HH + HH) * 4;
    const int SAB_SMEM  = (4 * SS * RS + 2 * 32 * RS) * 4;

    cudaFuncSetAttribute(gine_kernel, cudaFuncAttributeMaxDynamicSharedMemorySize, GINE_SMEM);
    cudaFuncSetAttribute(sab_kernel, cudaFuncAttributeMaxDynamicSharedMemorySize, SAB_SMEM);

    // 3-launch prologue (hist + weight split fused) -> gine at launch index 3
    edge_hist_whl_kernel<<<EE / 256 + 32 * 64, 256>>>(dst, gW1, gW2, Wq, Wk, Wv, Wo, fW1, fW2);
    dscan_kernel<<<BB, 64>>>();
    edge_scatter_gather_kernel<<<EE / 256, 256>>>(dst, src, edge_feat);

    for (int l = 0; l < LG; l++) {
        gine_kernel<<<BB, NT, GINE_SMEM>>>(node_feat, W_in, b_in, W_e, b_e,
                                           l, gb1 + l * HH,
                                           4 + l, gb2 + l * HH,
                                           l == 0 ? 0 : 1);
        bn_finalize_kernel<<<1, HH>>>(bn_g + l * HH, bn_b + l * HH);
    }

    for (int l = 0; l < LSS; l++) {
        sab_kernel<<<BB, NTS, SAB_SMEM>>>(8 + l * 12,
                                          fb1 + l * DFF, fb2 + l * HH,
                                          l1g + l * HH, l1b + l * HH,
                                          l2g + l * HH, l2b + l * HH,
                                          lengths,
                                          (l == LSS - 1) ? (float*)d_out : nullptr,
                                          l == 0 ? 1 : 0);
    }
}

// round 14
// speedup vs baseline: 1.0146x; 1.0146x over previous
#include <cuda_runtime.h>
#include <math_constants.h>
#include <cstdint>

#define NN  131072      // nodes = B*S
#define HH  128         // hidden
#define EE  1048576     // edges
#define BB  2048        // molecules
#define SS  64          // nodes per molecule
#define NF  74          // input node features
#define DFF 512         // ffn hidden
#define LG  4           // gine layers
#define LSS 2           // sab layers
#define NH  8           // heads
#define DH  16          // head dim
#define NT  256         // threads per CTA
#define EPM 1024        // edge slots per molecule
#define RS  136         // padded row stride (floats) for 64x128 smem tiles
#define RS4 34          // float4s per padded row
#define WRS 264         // padded row stride for hi|lo weight chunks (8 mod 32)

typedef unsigned long long ull;

#define PACK2(out, a)  asm("mov.b64 %0, {%1, %1};" : "=l"(out) : "r"(__float_as_uint(a)))
#define FFMA2(acc, a, b) asm("fma.rn.f32x2 %0, %1, %2, %0;" : "+l"(acc) : "l"(a), "l"(b))
#define UNPK2(lo, hi, in) do { unsigned _l, _h; \
    asm("mov.b64 {%0, %1}, %2;" : "=r"(_l), "=r"(_h) : "l"(in)); \
    lo = __uint_as_float(_l); hi = __uint_as_float(_h); } while (0)

#define CP_ASYNC16(s, g) asm volatile("cp.async.cg.shared.global [%0], [%1], 16;" \
    :: "r"(s), "l"(g))
#define CP_COMMIT() asm volatile("cp.async.commit_group;" ::: "memory")
#define CP_WAIT0() asm volatile("cp.async.wait_group 0;" ::: "memory")
#define CP_WAIT1() asm volatile("cp.async.wait_group 1;" ::: "memory")
#define CP_WAIT2() asm volatile("cp.async.wait_group 2;" ::: "memory")
#define CP_WAIT3() asm volatile("cp.async.wait_group 3;" ::: "memory")

#define TF32(o, f_) asm("cvt.rna.tf32.f32 %0, %1;" : "=r"(o) : "f"(f_))
#define MMA_TF32(d, a, b0_, b1_) \
    asm volatile("mma.sync.aligned.m16n8k8.row.col.f32.tf32.tf32.f32 " \
        "{%0,%1,%2,%3},{%4,%5,%6,%7},{%8,%9},{%0,%1,%2,%3};" \
        : "+f"(d[0]), "+f"(d[1]), "+f"(d[2]), "+f"(d[3]) \
        : "r"(a[0]), "r"(a[1]), "r"(a[2]), "r"(a[3]), "r"(b0_), "r"(b1_))

// ---------------- scratch (device globals) -----------------------------------
__device__ __align__(16) float g_h[NN * HH];
__device__ __align__(16) float g_z[NN * HH];
__device__ __align__(16) float g_sum[HH];
__device__ __align__(16) float g_sumsq[HH];
__device__ __align__(16) float g_bn_a[HH];
__device__ __align__(16) float g_bn_c[HH];
__device__ int g_dcnt[NN];
__device__ int g_dfill[NN];
__device__ int g_dstart[BB * 65];
__device__ __align__(16) float4 g_efs[BB * EPM];
__device__ unsigned char g_srcs[BB * EPM];
// pre-split weights: 32 slices, each 128 rows x (128 hi | 128 lo)
__device__ __align__(16) float g_whl[32 * 128 * 256];

// ---------------- weight chunk streaming -------------------------------------
// cp.async a 16-row x 256-col (hi|lo) chunk into padded-stride smem
__device__ __forceinline__ void cp_whl(const float* __restrict__ g, float* __restrict__ s)
{
    unsigned sa = (unsigned)__cvta_generic_to_shared(s);
#pragma unroll
    for (int u = threadIdx.x; u < 1024; u += NT) {
        int row = u >> 6;       // 0..15
        int c4 = u & 63;        // 0..63
        CP_ASYNC16(sa + (row * (WRS / 4) + c4) * 16, g + row * 256 + c4 * 4);
    }
}

// plain fp32 W chunk (for sgemm_var / input projection)
__device__ __forceinline__ void cp_chunk_rows(const float* __restrict__ g, int gstride,
                                              float* __restrict__ s, int rows)
{
    unsigned sa = (unsigned)__cvta_generic_to_shared(s);
    int lim = rows * 32;
    for (int u = threadIdx.x; u < lim; u += NT) {
        int row = u >> 5;
        int col4 = u & 31;
        CP_ASYNC16(sa + (row * RS4 + col4) * 16, g + row * gstride + col4 * 4);
    }
}

// ---------------- core MMA body for one 16-row chunk -------------------------
#define HL_CHUNK_BODY(A_, Wc_, cbase_, acc_) do { \
    _Pragma("unroll") \
    for (int ks = 0; ks < 2; ks++) { \
        int klo = ks * 8; \
        const float* Ar = (A_) + ra * RS + (cbase_) + klo + tig; \
        float a0f = Ar[0]; \
        float a2f = Ar[4]; \
        float a1f = Ar[8 * RS]; \
        float a3f = Ar[8 * RS + 4]; \
        unsigned ah[4], al[4]; \
        TF32(ah[0], a0f); TF32(ah[1], a1f); TF32(ah[2], a2f); TF32(ah[3], a3f); \
        float r0 = a0f - __uint_as_float(ah[0]); \
        float r1 = a1f - __uint_as_float(ah[1]); \
        float r2 = a2f - __uint_as_float(ah[2]); \
        float r3 = a3f - __uint_as_float(ah[3]); \
        TF32(al[0], r0); TF32(al[1], r1); TF32(al[2], r2); TF32(al[3], r3); \
        const float* Wh0 = (Wc_) + (klo + tig) * WRS; \
        const float* Wh1 = (Wc_) + (klo + tig + 4) * WRS; \
        _Pragma("unroll") \
        for (int j = 0; j < 8; j++) { \
            int n0 = colBase + j * 8 + g; \
            unsigned bh0 = __float_as_uint(Wh0[n0]); \
            unsigned bh1 = __float_as_uint(Wh1[n0]); \
            unsigned bl0 = __float_as_uint(Wh0[128 + n0]); \
            unsigned bl1 = __float_as_uint(Wh1[128 + n0]); \
            MMA_TF32(acc_[j], ah, bh0, bh1); \
            MMA_TF32(acc_[j], ah, bl0, bl1); \
            MMA_TF32(acc_[j], al, bh0, bh1); \
        } \
    } \
} while (0)

#define HL_EPILOG(bias_, relu_, accum_, C_, acc_) do { \
    _Pragma("unroll") \
    for (int j = 0; j < 8; j++) { \
        int cc = colBase + j * 8 + 2 * tig; \
        float v0 = acc_[j][0], v1 = acc_[j][1], v2 = acc_[j][2], v3 = acc_[j][3]; \
        if (bias_) { \
            float bA = (bias_)[cc], bB = (bias_)[cc + 1]; \
            v0 += bA; v1 += bB; v2 += bA; v3 += bB; \
        } \
        if (relu_) { \
            v0 = fmaxf(v0, 0.f); v1 = fmaxf(v1, 0.f); \
            v2 = fmaxf(v2, 0.f); v3 = fmaxf(v3, 0.f); \
        } \
        if (accum_) { \
            v0 += (C_)[ra * RS + cc]; \
            v1 += (C_)[ra * RS + cc + 1]; \
            v2 += (C_)[(ra + 8) * RS + cc]; \
            v3 += (C_)[(ra + 8) * RS + cc + 1]; \
        } \
        (C_)[ra * RS + cc]           = v0; \
        (C_)[ra * RS + cc + 1]       = v1; \
        (C_)[(ra + 8) * RS + cc]     = v2; \
        (C_)[(ra + 8) * RS + cc + 1] = v3; \
    } \
} while (0)

// depth-2 streamed GEMM (GINE; 2 CTAs/SM hide residual latency)
__device__ __forceinline__ void sgemm64hl(const float* __restrict__ A,
                                          const float* __restrict__ Whl,
                                          const float* __restrict__ bias,
                                          float* __restrict__ C,
                                          float* __restrict__ wbuf,
                                          bool relu, bool accum)
{
    int tid = threadIdx.x;
    int w = tid >> 5;
    int lane = tid & 31;
    int g = lane >> 2;
    int tig = lane & 3;
    int ra = (w & 3) * 16 + g;
    int colBase = (w >> 2) * 64;

    float acc[8][4];
#pragma unroll
    for (int j = 0; j < 8; j++)
#pragma unroll
        for (int q = 0; q < 4; q++) acc[j][q] = 0.0f;

    cp_whl(Whl, wbuf);
    CP_COMMIT();
#pragma unroll
    for (int c = 0; c < 8; c++) {
        if (c < 7) {
            cp_whl(Whl + (c + 1) * 16 * 256, wbuf + ((c + 1) & 1) * 16 * WRS);
            CP_COMMIT();
            CP_WAIT1();
        } else {
            CP_WAIT0();
        }
        __syncthreads();
        const float* Wc = wbuf + (c & 1) * 16 * WRS;
        HL_CHUNK_BODY(A, Wc, c * 16, acc);
        __syncthreads();
    }
    HL_EPILOG(bias, relu, accum, C, acc);
}

// depth-4 streamed GEMM (SAB; 1 CTA/SM, prefetch distance 3 hides L2 latency)
__device__ __forceinline__ void sgemm64hl4(const float* __restrict__ A,
                                           const float* __restrict__ Whl,
                                           const float* __restrict__ bias,
                                           float* __restrict__ C,
                                           float* __restrict__ wbuf,
                                           bool relu, bool accum)
{
    int tid = threadIdx.x;
    int w = tid >> 5;
    int lane = tid & 31;
    int g = lane >> 2;
    int tig = lane & 3;
    int ra = (w & 3) * 16 + g;
    int colBase = (w >> 2) * 64;

    float acc[8][4];
#pragma unroll
    for (int j = 0; j < 8; j++)
#pragma unroll
        for (int q = 0; q < 4; q++) acc[j][q] = 0.0f;

    cp_whl(Whl, wbuf);
    CP_COMMIT();
    cp_whl(Whl + 1 * 16 * 256, wbuf + 1 * 16 * WRS);
    CP_COMMIT();
    cp_whl(Whl + 2 * 16 * 256, wbuf + 2 * 16 * WRS);
    CP_COMMIT();
#pragma unroll
    for (int c = 0; c < 8; c++) {
        if (c < 5) {
            cp_whl(Whl + (c + 3) * 16 * 256, wbuf + ((c + 3) & 3) * 16 * WRS);
            CP_COMMIT();
            CP_WAIT3();
        } else if (c == 5) {
            CP_WAIT2();
        } else if (c == 6) {
            CP_WAIT1();
        } else {
            CP_WAIT0();
        }
        __syncthreads();
        const float* Wc = wbuf + (c & 3) * 16 * WRS;
        HL_CHUNK_BODY(A, Wc, c * 16, acc);
        __syncthreads();
    }
    HL_EPILOG(bias, relu, accum, C, acc);
}

// ---------------- SIMT variable-K GEMM (input projection, K=74) --------------
#define GEMM_K4(ap0_, ap1_, ap2_, ap3_, Wrow_, accv_) do { \
    ulonglong2 w01_ = *reinterpret_cast<const ulonglong2*>(Wrow_); \
    ulonglong2 w23_ = *reinterpret_cast<const ulonglong2*>((Wrow_) + 4); \
    FFMA2(accv_[0][0], ap0_, w01_.x); FFMA2(accv_[0][1], ap0_, w01_.y); \
    FFMA2(accv_[0][2], ap0_, w23_.x); FFMA2(accv_[0][3], ap0_, w23_.y); \
    FFMA2(accv_[1][0], ap1_, w01_.x); FFMA2(accv_[1][1], ap1_, w01_.y); \
    FFMA2(accv_[1][2], ap1_, w23_.x); FFMA2(accv_[1][3], ap1_, w23_.y); \
    FFMA2(accv_[2][0], ap2_, w01_.x); FFMA2(accv_[2][1], ap2_, w01_.y); \
    FFMA2(accv_[2][2], ap2_, w23_.x); FFMA2(accv_[2][3], ap2_, w23_.y); \
    FFMA2(accv_[3][0], ap3_, w01_.x); FFMA2(accv_[3][1], ap3_, w01_.y); \
    FFMA2(accv_[3][2], ap3_, w23_.x); FFMA2(accv_[3][3], ap3_, w23_.y); \
} while (0)

__device__ __forceinline__ void sgemm_var(const float* __restrict__ A, int lda, int K,
                                          const float* __restrict__ Wg, int gstride,
                                          const float* __restrict__ bias,
                                          float* __restrict__ C,
                                          float* __restrict__ wbuf)
{
    int tid = threadIdx.x;
    int r0 = (tid >> 4) * 4;
    int c0 = (tid & 15) * 8;
    ull acc[4][4];
#pragma unroll
    for (int i = 0; i < 4; i++)
#pragma unroll
        for (int j = 0; j < 4; j++) acc[i][j] = 0ULL;

    int nch = (K + 31) / 32;
    cp_chunk_rows(Wg, gstride, wbuf, K < 32 ? K : 32);
    CP_COMMIT();
    for (int c = 0; c < nch; c++) {
        if (c + 1 < nch) {
            int rows = K - (c + 1) * 32;
            if (rows > 32) rows = 32;
            cp_chunk_rows(Wg + (c + 1) * 32 * gstride, gstride,
                          wbuf + ((c + 1) & 1) * 32 * RS, rows);
            CP_COMMIT();
            CP_WAIT1();
        } else {
            CP_WAIT0();
        }
        __syncthreads();
        const float* Wc = wbuf + (c & 1) * 32 * RS;
        int kbase = c * 32;
        int kn = K - kbase;
        if (kn > 32) kn = 32;
        for (int kk = 0; kk < kn; kk++) {
            ull p0, p1, p2, p3;
            float v0 = A[(r0 + 0) * lda + kbase + kk];
            float v1 = A[(r0 + 1) * lda + kbase + kk];
            float v2 = A[(r0 + 2) * lda + kbase + kk];
            float v3 = A[(r0 + 3) * lda + kbase + kk];
            PACK2(p0, v0); PACK2(p1, v1); PACK2(p2, v2); PACK2(p3, v3);
            GEMM_K4(p0, p1, p2, p3, &Wc[kk * RS + c0], acc);
        }
        __syncthreads();
    }
#pragma unroll
    for (int i = 0; i < 4; i++)
#pragma unroll
        for (int j = 0; j < 4; j++) {
            float lo, hi;
            UNPK2(lo, hi, acc[i][j]);
            lo += bias[c0 + 2 * j];
            hi += bias[c0 + 2 * j + 1];
            C[(r0 + i) * RS + c0 + 2 * j]     = lo;
            C[(r0 + i) * RS + c0 + 2 * j + 1] = hi;
        }
}

// per-row layernorm over 64 rows (8 warps); X,O stride RS
__device__ __forceinline__ void ln_rows(const float* __restrict__ X, float* __restrict__ O,
                                        const float* __restrict__ gg, const float* __restrict__ bb)
{
    int wid = threadIdx.x >> 5;
    int lane = threadIdx.x & 31;
    for (int r = wid; r < SS; r += 8) {
        float v0 = X[r * RS + lane];
        float v1 = X[r * RS + lane + 32];
        float v2 = X[r * RS + lane + 64];
        float v3 = X[r * RS + lane + 96];
        float s = v0 + v1 + v2 + v3;
        float ss = v0 * v0 + v1 * v1 + v2 * v2 + v3 * v3;
#pragma unroll
        for (int o = 16; o; o >>= 1) {
            s += __shfl_xor_sync(0xffffffffu, s, o);
            ss += __shfl_xor_sync(0xffffffffu, ss, o);
        }
        float mu = s * (1.0f / HH);
        float var = ss * (1.0f / HH) - mu * mu;
        float inv = rsqrtf(var + 1e-5f);
        O[r * RS + lane]      = (v0 - mu) * inv * gg[lane]      + bb[lane];
        O[r * RS + lane + 32] = (v1 - mu) * inv * gg[lane + 32] + bb[lane + 32];
        O[r * RS + lane + 64] = (v2 - mu) * inv * gg[lane + 64] + bb[lane + 64];
        O[r * RS + lane + 96] = (v3 - mu) * inv * gg[lane + 96] + bb[lane + 96];
    }
}

// ---------------- prologue: edge hist + weight hi/lo split (fused) -----------
__global__ void edge_hist_whl_kernel(const int* __restrict__ dst,
                                     const float* __restrict__ gW1,
                                     const float* __restrict__ gW2,
                                     const float* __restrict__ Wq,
                                     const float* __restrict__ Wk,
                                     const float* __restrict__ Wv,
                                     const float* __restrict__ Wo,
                                     const float* __restrict__ fW1,
                                     const float* __restrict__ fW2)
{
    int b = blockIdx.x;
    if (b < EE / 256) {
        int e = b * 256 + threadIdx.x;
        atomicAdd(&g_dcnt[dst[e]], 1);      // g_dcnt zero at entry (invariant)
        return;
    }
    int sb = b - EE / 256;
    int s = sb >> 6;
    int i = (sb & 63) * 256 + threadIdx.x;
    int k = i >> 7;
    int j = i & 127;
    const float* srcp;
    if (s < 4) {
        srcp = gW1 + s * 16384 + k * 128 + j;
    } else if (s < 8) {
        srcp = gW2 + (s - 4) * 16384 + k * 128 + j;
    } else {
        int l = (s - 8) / 12;
        int t = (s - 8) % 12;
        if (t < 4) {
            const float* base = (t == 0) ? Wq : (t == 1) ? Wk : (t == 2) ? Wv : Wo;
            srcp = base + l * 16384 + k * 128 + j;
        } else if (t < 8) {
            int c = t - 4;
            srcp = fW1 + l * 65536 + k * 512 + c * 128 + j;
        } else {
            int c = t - 8;
            srcp = fW2 + l * 65536 + (c * 128 + k) * 128 + j;
        }
    }
    float v = *srcp;
    unsigned hi;
    TF32(hi, v);
    float lo = v - __uint_as_float(hi);
    unsigned lou;
    TF32(lou, lo);
    float* dstp = g_whl + s * 32768 + k * 256;
    dstp[j] = __uint_as_float(hi);
    dstp[128 + j] = __uint_as_float(lou);
}

__global__ void dscan_kernel()
{
    __shared__ int sh[64];
    int m = blockIdx.x;
    int t = threadIdx.x;
    int c = g_dcnt[m * 64 + t];
    sh[t] = c;
    __syncthreads();
    for (int off = 1; off < 64; off <<= 1) {
        int v = (t >= off) ? sh[t - off] : 0;
        __syncthreads();
        sh[t] += v;
        __syncthreads();
    }
    g_dstart[m * 65 + t] = sh[t] - c;
    if (t == 63) g_dstart[m * 65 + 64] = sh[63];
    g_dcnt[m * 64 + t] = 0;
    g_dfill[m * 64 + t] = 0;
}

__global__ void edge_scatter_gather_kernel(const int* __restrict__ dst,
                                           const int* __restrict__ src,
                                           const float* __restrict__ ef)
{
    int e = blockIdx.x * blockDim.x + threadIdx.x;
    if (e < EE) {
        int dv = dst[e];
        int p = atomicAdd(&g_dfill[dv], 1);
        int m = dv >> 6;
        int d = dv & 63;
        int slot = m * EPM + g_dstart[m * 65 + d] + p;
        g_efs[slot] = reinterpret_cast<const float4*>(ef)[e];
        g_srcs[slot] = (unsigned char)(src[e] & (SS - 1));
    }
}

// ---------------- GINE layer (1 molecule per CTA, 2 CTAs/SM) -----------------
__global__ void __launch_bounds__(NT, 2) gine_kernel(
                            const float* __restrict__ nf,
                            const float* __restrict__ Win, const float* __restrict__ bin,
                            const float* __restrict__ We, const float* __restrict__ be,
                            int s1, const float* __restrict__ b1,
                            int s2, const float* __restrict__ b2,
                            int mode)
{
    extern __shared__ float smem[];
    float* hb   = smem;                  // 64xRS (h; later reused as z1)
    float* ag   = hb + SS * RS;          // 64xRS (nf / z -> z2)
    float* wbuf = ag + SS * RS;          // 2x32xRS floats
    float* wesm = wbuf + 2 * 32 * RS;    // 4x128
    float* besm = wesm + 4 * HH;         // 128
    int m = blockIdx.x;
    int row0 = m * SS;
    int tid = threadIdx.x;
    const float* W1hl = g_whl + (size_t)s1 * 32768;
    const float* W2hl = g_whl + (size_t)s2 * 32768;

    {
        for (int i = tid; i < 4 * HH; i += NT) wesm[i] = We[i];
        if (tid < HH) besm[tid] = be[tid];
    }
    if (mode == 0) {
        for (int i = tid; i < SS * NF; i += NT) ag[i] = nf[row0 * NF + i];
        sgemm_var(ag, NF, NF, Win, HH, bin, hb, wbuf);
        __syncthreads();
        {
            float4* gh4 = reinterpret_cast<float4*>(g_h + row0 * HH);
            for (int i = tid; i < SS * 32; i += NT) {
                int r = i >> 5, c4 = i & 31;
                gh4[r * 32 + c4] = *reinterpret_cast<const float4*>(&hb[r * RS + c4 * 4]);
            }
        }
    } else {
        float4* gh4 = reinterpret_cast<float4*>(g_h + row0 * HH);
        const float4* gz4 = reinterpret_cast<const float4*>(g_z + row0 * HH);
        for (int i = tid; i < SS * 32; i += NT) {
            int rr = i >> 5, c4 = i & 31;
            int f0 = c4 * 4;
            float4 a = *reinterpret_cast<const float4*>(&g_bn_a[f0]);
            float4 c = *reinterpret_cast<const float4*>(&g_bn_c[f0]);
            float4 z = gz4[i];
            float4 h = gh4[i];
            float4 r;
            r.x = fmaxf(fmaf(z.x, a.x, c.x), 0.f) + h.x;
            r.y = fmaxf(fmaf(z.y, a.y, c.y), 0.f) + h.y;
            r.z = fmaxf(fmaf(z.z, a.z, c.z), 0.f) + h.z;
            r.w = fmaxf(fmaf(z.w, a.w, c.w), 0.f) + h.w;
            *reinterpret_cast<float4*>(&hb[rr * RS + c4 * 4]) = r;
            gh4[i] = r;
        }
    }
    __syncthreads();

    // message passing: 8 warps over 64 dst rows, atomic-free
    {
        int wid = tid >> 5, lane = tid & 31;
        int ebeg = m * EPM;
        const int* gd = g_dstart + m * 65;
        float wr[4][4], br[4];
#pragma unroll
        for (int q = 0; q < 4; q++) {
            int f = lane + 32 * q;
            wr[q][0] = wesm[f];
            wr[q][1] = wesm[HH + f];
            wr[q][2] = wesm[2 * HH + f];
            wr[q][3] = wesm[3 * HH + f];
            br[q] = besm[f];
        }
        for (int d = wid; d < SS; d += 8) {
            float a0 = 0.f, a1 = 0.f, a2 = 0.f, a3 = 0.f;
            int b = gd[d], en = gd[d + 1];
            for (int idx = b; idx < en; idx++) {
                float4 f4 = g_efs[ebeg + idx];
                int s = g_srcs[ebeg + idx];
                const float* hr = &hb[s * RS];
                float m0 = hr[lane]      + f4.x * wr[0][0] + f4.y * wr[0][1] + f4.z * wr[0][2] + f4.w * wr[0][3] + br[0];
                float m1 = hr[lane + 32] + f4.x * wr[1][0] + f4.y * wr[1][1] + f4.z * wr[1][2] + f4.w * wr[1][3] + br[1];
                float m2_ = hr[lane + 64] + f4.x * wr[2][0] + f4.y * wr[2][1] + f4.z * wr[2][2] + f4.w * wr[2][3] + br[2];
                float m3 = hr[lane + 96] + f4.x * wr[3][0] + f4.y * wr[3][1] + f4.z * wr[3][2] + f4.w * wr[3][3] + br[3];
                a0 += fmaxf(m0, 0.f);
                a1 += fmaxf(m1, 0.f);
                a2 += fmaxf(m2_, 0.f);
                a3 += fmaxf(m3, 0.f);
            }
            ag[d * RS + lane]      = a0 + hb[d * RS + lane];
            ag[d * RS + lane + 32] = a1 + hb[d * RS + lane + 32];
            ag[d * RS + lane + 64] = a2 + hb[d * RS + lane + 64];
            ag[d * RS + lane + 96] = a3 + hb[d * RS + lane + 96];
        }
    }
    sgemm64hl(ag, W1hl, b1, hb, wbuf, true, false);    // z1 = relu(z@W1+b1)
    __syncthreads();
    sgemm64hl(hb, W2hl, b2, ag, wbuf, false, false);   // z2 = z1@W2+b2
    __syncthreads();

    {   // BN partial stats
        int f = tid & 127;
        int c = tid >> 7;
        float s = 0.f, ss = 0.f;
        for (int r = c * 32; r < c * 32 + 32; r++) {
            float v = ag[r * RS + f];
            s += v;
            ss += v * v;
        }
        atomicAdd(&g_sum[f], s);
        atomicAdd(&g_sumsq[f], ss);
    }
    {
        float4* gz4 = reinterpret_cast<float4*>(g_z + row0 * HH);
        for (int i = tid; i < SS * 32; i += NT) {
            int r = i >> 5, c4 = i & 31;
            gz4[r * 32 + c4] = *reinterpret_cast<const float4*>(&ag[r * RS + c4 * 4]);
        }
    }
}

__global__ void bn_finalize_kernel(const float* __restrict__ bng, const float* __restrict__ bnb)
{
    int f = threadIdx.x;
    float mu = g_sum[f] * (1.0f / NN);
    float var = g_sumsq[f] * (1.0f / NN) - mu * mu;
    float inv = rsqrtf(var + 1e-5f);
    float a = inv * bng[f];
    g_bn_a[f] = a;
    g_bn_c[f] = bnb[f] - mu * a;
    g_sum[f] = 0.0f;
    g_sumsq[f] = 0.0f;
}

// ---------------- SAB layer (NT=256, depth-4 streamed GEMMs) -----------------
__global__ void __launch_bounds__(NT) sab_kernel(
                           int sbase,
                           const float* __restrict__ b1, const float* __restrict__ b2,
                           const float* __restrict__ l1g, const float* __restrict__ l1b,
                           const float* __restrict__ l2g, const float* __restrict__ l2b,
                           const int* __restrict__ lengths, float* __restrict__ out,
                           int fuse_bn)
{
    extern __shared__ float smem[];
    float* xb   = smem;                  // 64xRS
    float* qb   = xb + SS * RS;
    float* kb   = qb + SS * RS;
    float* vb   = kb + SS * RS;
    float* wbuf = vb + SS * RS;          // 4x16xWRS floats; aliased as score scratch
    float* scr  = wbuf;                  // 64x65 fits (4160 <= 16896)
    int m = blockIdx.x;
    int row0 = m * SS;
    int tid = threadIdx.x;
    const float* Qhl = g_whl + (size_t)(sbase + 0) * 32768;
    const float* Khl = g_whl + (size_t)(sbase + 1) * 32768;
    const float* Vhl = g_whl + (size_t)(sbase + 2) * 32768;
    const float* Ohl = g_whl + (size_t)(sbase + 3) * 32768;

    {
        const float4* gx4 = reinterpret_cast<const float4*>(g_h + row0 * HH);
        if (fuse_bn) {
            const float4* gz4 = reinterpret_cast<const float4*>(g_z + row0 * HH);
            for (int i = tid; i < SS * 32; i += NT) {
                int rr = i >> 5, c4 = i & 31;
                int f0 = c4 * 4;
                float4 a = *reinterpret_cast<const float4*>(&g_bn_a[f0]);
                float4 c = *reinterpret_cast<const float4*>(&g_bn_c[f0]);
                float4 z = gz4[i];
                float4 h = gx4[i];
                float4 r;
                r.x = fmaxf(fmaf(z.x, a.x, c.x), 0.f) + h.x;
                r.y = fmaxf(fmaf(z.y, a.y, c.y), 0.f) + h.y;
                r.z = fmaxf(fmaf(z.z, a.z, c.z), 0.f) + h.z;
                r.w = fmaxf(fmaf(z.w, a.w, c.w), 0.f) + h.w;
                *reinterpret_cast<float4*>(&xb[rr * RS + c4 * 4]) = r;
            }
        } else {
            for (int i = tid; i < SS * 32; i += NT) {
                int rr = i >> 5, c4 = i & 31;
                *reinterpret_cast<float4*>(&xb[rr * RS + c4 * 4]) = gx4[i];
            }
        }
    }
    __syncthreads();
    ln_rows(xb, vb, l1g, l1b);                 // xn -> vb (temp)
    sgemm64hl4(vb, Qhl, nullptr, qb, wbuf, false, false);   // q = xn @ Wq
    sgemm64hl4(xb, Khl, nullptr, kb, wbuf, false, false);   // k = x @ Wk
    sgemm64hl4(xb, Vhl, nullptr, vb, wbuf, false, false);   // v = x @ Wv
    __syncthreads();

    int len = lengths[m];
    const float scale = 0.25f;
    for (int hh = 0; hh < NH; hh++) {
        {   // scores
            int i = tid >> 2;
            int j0 = (tid & 3) * 16;
            ull q2[8];
            const ull* qrow = reinterpret_cast<const ull*>(&qb[i * RS + hh * DH]);
#pragma unroll
            for (int d2 = 0; d2 < 8; d2++) q2[d2] = qrow[d2];
#pragma unroll
            for (int jj = 0; jj < 16; jj++) {
                int j = j0 + jj;
                const ull* krow = reinterpret_cast<const ull*>(&kb[j * RS + hh * DH]);
                ull s2 = 0ULL;
#pragma unroll
                for (int d2 = 0; d2 < 8; d2++) FFMA2(s2, q2[d2], krow[d2]);
                float lo, hi;
                UNPK2(lo, hi, s2);
                float sdot = lo + hi;
                scr[i * 65 + j] = (i < len && j < len) ? sdot * scale : -CUDART_INF_F;
            }
        }
        __syncthreads();
        {   // softmax rows
            int wid = tid >> 5, lane = tid & 31;
            for (int r = wid; r < SS; r += 8) {
                float x0 = scr[r * 65 + lane];
                float x1 = scr[r * 65 + lane + 32];
                float mx = fmaxf(x0, x1);
#pragma unroll
                for (int o = 16; o; o >>= 1) mx = fmaxf(mx, __shfl_xor_sync(0xffffffffu, mx, o));
                float e0 = (r < len && lane < len)      ? __expf(x0 - mx) : 0.f;
                float e1 = (r < len && lane + 32 < len) ? __expf(x1 - mx) : 0.f;
                float sm = e0 + e1;
#pragma unroll
                for (int o = 16; o; o >>= 1) sm += __shfl_xor_sync(0xffffffffu, sm, o);
                float rinv = (sm > 0.f) ? (1.0f / sm) : 0.f;
                scr[r * 65 + lane]      = e0 * rinv;
                scr[r * 65 + lane + 32] = e1 * rinv;
            }
        }
        __syncthreads();
        {   // att_h = alpha @ v_h, overwrite dead q_h columns
            int i2 = tid >> 2;
            int d0 = (tid & 3) * 4;
            ull acc0 = 0ULL, acc1 = 0ULL;
#pragma unroll 8
            for (int j = 0; j < SS; j++) {
                float al = scr[i2 * 65 + j];
                ull al2;
                PACK2(al2, al);
                const ull* vr = reinterpret_cast<const ull*>(&vb[j * RS + hh * DH + d0]);
                FFMA2(acc0, al2, vr[0]);
                FFMA2(acc1, al2, vr[1]);
            }
            float* qr = &qb[i2 * RS + hh * DH + d0];
            float lo, hi;
            UNPK2(lo, hi, acc0); qr[0] = lo; qr[1] = hi;
            UNPK2(lo, hi, acc1); qr[2] = lo; qr[3] = hi;
        }
        __syncthreads();
    }

    sgemm64hl4(qb, Ohl, nullptr, xb, wbuf, false, true);    // x += att @ Wo
    __syncthreads();
    ln_rows(xb, kb, l2g, l2b);                              // xn2 -> kb
    for (int c = 0; c < 4; c++) {
        const float* F1hl = g_whl + (size_t)(sbase + 4 + c) * 32768;
        const float* F2hl = g_whl + (size_t)(sbase + 8 + c) * 32768;
        sgemm64hl4(kb, F1hl, b1 + c * HH, qb, wbuf, true, false);
        sgemm64hl4(qb, F2hl, (c == 0) ? b2 : nullptr, xb, wbuf, false, true);
    }
    __syncthreads();

    float* op = out ? out : g_h;
    {
        float4* o4 = reinterpret_cast<float4*>(op + row0 * HH);
        for (int i = tid; i < SS * 32; i += NT) {
            int r = i >> 5, c4 = i & 31;
            o4[r * 32 + c4] = *reinterpret_cast<const float4*>(&xb[r * RS + c4 * 4]);
        }
    }
}

// ---------------- launch ------------------------------------------------------
extern "C" void kernel_launch(void* const* d_in, const int* in_sizes, int n_in,
                              void* d_out, int out_size)
{
    const float* node_feat = (const float*)d_in[0];
    const float* edge_feat = (const float*)d_in[1];
    const float* W_in   = (const float*)d_in[2];
    const float* b_in   = (const float*)d_in[3];
    const float* W_e    = (const float*)d_in[4];
    const float* b_e    = (const float*)d_in[5];
    const float* gW1    = (const float*)d_in[6];
    const float* gb1    = (const float*)d_in[7];
    const float* gW2    = (const float*)d_in[8];
    const float* gb2    = (const float*)d_in[9];
    const float* bn_g   = (const float*)d_in[10];
    const float* bn_b   = (const float*)d_in[11];
    const float* Wq     = (const float*)d_in[12];
    const float* Wk     = (const float*)d_in[13];
    const float* Wv     = (const float*)d_in[14];
    const float* Wo     = (const float*)d_in[15];
    const float* fW1    = (const float*)d_in[16];
    const float* fb1    = (const float*)d_in[17];
    const float* fW2    = (const float*)d_in[18];
    const float* fb2    = (const float*)d_in[19];
    const float* l1g    = (const float*)d_in[20];
    const float* l1b    = (const float*)d_in[21];
    const float* l2g    = (const float*)d_in[22];
    const float* l2b    = (const float*)d_in[23];
    const int*   src    = (const int*)d_in[24];
    const int*   dst    = (const int*)d_in[25];
    const int*   lengths= (const int*)d_in[26];

    const int GINE_SMEM = (2 * SS * RS + 2 * 32 * RS + 4 * HH + HH) * 4;
    const int SAB_SMEM  = (4 * SS * RS + 4 * 16 * WRS) * 4;

    cudaFuncSetAttribute(gine_kernel, cudaFuncAttributeMaxDynamicSharedMemorySize, GINE_SMEM);
    cudaFuncSetAttribute(sab_kernel, cudaFuncAttributeMaxDynamicSharedMemorySize, SAB_SMEM);

    // 3-launch prologue (hist + weight split fused) -> gine at launch index 3
    edge_hist_whl_kernel<<<EE / 256 + 32 * 64, 256>>>(dst, gW1, gW2, Wq, Wk, Wv, Wo, fW1, fW2);
    dscan_kernel<<<BB, 64>>>();
    edge_scatter_gather_kernel<<<EE / 256, 256>>>(dst, src, edge_feat);

    for (int l = 0; l < LG; l++) {
        gine_kernel<<<BB, NT, GINE_SMEM>>>(node_feat, W_in, b_in, W_e, b_e,
                                           l, gb1 + l * HH,
                                           4 + l, gb2 + l * HH,
                                           l == 0 ? 0 : 1);
        bn_finalize_kernel<<<1, HH>>>(bn_g + l * HH, bn_b + l * HH);
    }

    for (int l = 0; l < LSS; l++) {
        sab_kernel<<<BB, NT, SAB_SMEM>>>(8 + l * 12,
                                         fb1 + l * DFF, fb2 + l * HH,
                                         l1g + l * HH, l1b + l * HH,
                                         l2g + l * HH, l2b + l * HH,
                                         lengths,
                                         (l == LSS - 1) ? (float*)d_out : nullptr,
                                         l == 0 ? 1 : 0);
    }
}

// round 15
// speedup vs baseline: 1.0238x; 1.0091x over previous
#include <cuda_runtime.h>
#include <math_constants.h>
#include <cstdint>

#define NN  131072      // nodes = B*S
#define HH  128         // hidden
#define EE  1048576     // edges
#define BB  2048        // molecules
#define SS  64          // nodes per molecule
#define NF  74          // input node features
#define DFF 512         // ffn hidden
#define LG  4           // gine layers
#define LSS 2           // sab layers
#define NH  8           // heads
#define DH  16          // head dim
#define NT  256         // threads per CTA
#define EPM 1024        // edge slots per molecule
#define RS  136         // padded row stride (floats) for 64x128 smem tiles
#define RS4 34          // float4s per padded row
#define WRS 264         // padded row stride for hi|lo weight chunks (8 mod 32)

typedef unsigned long long ull;

#define PACK2(out, a)  asm("mov.b64 %0, {%1, %1};" : "=l"(out) : "r"(__float_as_uint(a)))
#define FFMA2(acc, a, b) asm("fma.rn.f32x2 %0, %1, %2, %0;" : "+l"(acc) : "l"(a), "l"(b))
#define UNPK2(lo, hi, in) do { unsigned _l, _h; \
    asm("mov.b64 {%0, %1}, %2;" : "=r"(_l), "=r"(_h) : "l"(in)); \
    lo = __uint_as_float(_l); hi = __uint_as_float(_h); } while (0)

#define CP_ASYNC16(s, g) asm volatile("cp.async.cg.shared.global [%0], [%1], 16;" \
    :: "r"(s), "l"(g))
#define CP_COMMIT() asm volatile("cp.async.commit_group;" ::: "memory")
#define CP_WAIT0() asm volatile("cp.async.wait_group 0;" ::: "memory")
#define CP_WAIT1() asm volatile("cp.async.wait_group 1;" ::: "memory")
#define CP_WAIT2() asm volatile("cp.async.wait_group 2;" ::: "memory")

#define TF32(o, f_) asm("cvt.rna.tf32.f32 %0, %1;" : "=r"(o) : "f"(f_))
#define MMA_TF32(d, a, b0_, b1_) \
    asm volatile("mma.sync.aligned.m16n8k8.row.col.f32.tf32.tf32.f32 " \
        "{%0,%1,%2,%3},{%4,%5,%6,%7},{%8,%9},{%0,%1,%2,%3};" \
        : "+f"(d[0]), "+f"(d[1]), "+f"(d[2]), "+f"(d[3]) \
        : "r"(a[0]), "r"(a[1]), "r"(a[2]), "r"(a[3]), "r"(b0_), "r"(b1_))

// ---------------- scratch (device globals) -----------------------------------
__device__ __align__(16) float g_h[NN * HH];
__device__ __align__(16) float g_z[NN * HH];
__device__ __align__(16) float g_sum[HH];
__device__ __align__(16) float g_sumsq[HH];
__device__ __align__(16) float g_bn_a[HH];
__device__ __align__(16) float g_bn_c[HH];
__device__ int g_dcnt[NN];
__device__ int g_dfill[NN];
__device__ int g_dstart[BB * 65];
__device__ __align__(16) float4 g_efs[BB * EPM];
__device__ unsigned char g_srcs[BB * EPM];
// pre-split weights: 32 slices, each 128 rows x (128 hi | 128 lo)
__device__ __align__(16) float g_whl[32 * 128 * 256];

// ---------------- weight chunk streaming -------------------------------------
// cp.async a 16-row x 256-col (hi|lo) chunk into padded-stride smem
__device__ __forceinline__ void cp_whl(const float* __restrict__ g, float* __restrict__ s)
{
    unsigned sa = (unsigned)__cvta_generic_to_shared(s);
#pragma unroll
    for (int u = threadIdx.x; u < 1024; u += NT) {
        int row = u >> 6;       // 0..15
        int c4 = u & 63;        // 0..63
        CP_ASYNC16(sa + (row * (WRS / 4) + c4) * 16, g + row * 256 + c4 * 4);
    }
}

// plain fp32 W chunk (for sgemm_var / input projection)
__device__ __forceinline__ void cp_chunk_rows(const float* __restrict__ g, int gstride,
                                              float* __restrict__ s, int rows)
{
    unsigned sa = (unsigned)__cvta_generic_to_shared(s);
    int lim = rows * 32;
    for (int u = threadIdx.x; u < lim; u += NT) {
        int row = u >> 5;
        int col4 = u & 31;
        CP_ASYNC16(sa + (row * RS4 + col4) * 16, g + row * gstride + col4 * 4);
    }
}

// ---------------- core MMA body for one 16-row chunk -------------------------
#define HL_CHUNK_BODY(A_, Wc_, cbase_, acc_) do { \
    _Pragma("unroll") \
    for (int ks = 0; ks < 2; ks++) { \
        int klo = ks * 8; \
        const float* Ar = (A_) + ra * RS + (cbase_) + klo + tig; \
        float a0f = Ar[0]; \
        float a2f = Ar[4]; \
        float a1f = Ar[8 * RS]; \
        float a3f = Ar[8 * RS + 4]; \
        unsigned ah[4], al[4]; \
        TF32(ah[0], a0f); TF32(ah[1], a1f); TF32(ah[2], a2f); TF32(ah[3], a3f); \
        float r0 = a0f - __uint_as_float(ah[0]); \
        float r1 = a1f - __uint_as_float(ah[1]); \
        float r2 = a2f - __uint_as_float(ah[2]); \
        float r3 = a3f - __uint_as_float(ah[3]); \
        TF32(al[0], r0); TF32(al[1], r1); TF32(al[2], r2); TF32(al[3], r3); \
        const float* Wh0 = (Wc_) + (klo + tig) * WRS; \
        const float* Wh1 = (Wc_) + (klo + tig + 4) * WRS; \
        _Pragma("unroll") \
        for (int j = 0; j < 8; j++) { \
            int n0 = colBase + j * 8 + g; \
            unsigned bh0 = __float_as_uint(Wh0[n0]); \
            unsigned bh1 = __float_as_uint(Wh1[n0]); \
            unsigned bl0 = __float_as_uint(Wh0[128 + n0]); \
            unsigned bl1 = __float_as_uint(Wh1[128 + n0]); \
            MMA_TF32(acc_[j], ah, bh0, bh1); \
            MMA_TF32(acc_[j], ah, bl0, bl1); \
            MMA_TF32(acc_[j], al, bh0, bh1); \
        } \
    } \
} while (0)

#define HL_EPILOG(bias_, relu_, accum_, C_, acc_) do { \
    _Pragma("unroll") \
    for (int j = 0; j < 8; j++) { \
        int cc = colBase + j * 8 + 2 * tig; \
        float v0 = acc_[j][0], v1 = acc_[j][1], v2 = acc_[j][2], v3 = acc_[j][3]; \
        if (bias_) { \
            float bA = (bias_)[cc], bB = (bias_)[cc + 1]; \
            v0 += bA; v1 += bB; v2 += bA; v3 += bB; \
        } \
        if (relu_) { \
            v0 = fmaxf(v0, 0.f); v1 = fmaxf(v1, 0.f); \
            v2 = fmaxf(v2, 0.f); v3 = fmaxf(v3, 0.f); \
        } \
        if (accum_) { \
            v0 += (C_)[ra * RS + cc]; \
            v1 += (C_)[ra * RS + cc + 1]; \
            v2 += (C_)[(ra + 8) * RS + cc]; \
            v3 += (C_)[(ra + 8) * RS + cc + 1]; \
        } \
        (C_)[ra * RS + cc]           = v0; \
        (C_)[ra * RS + cc + 1]       = v1; \
        (C_)[(ra + 8) * RS + cc]     = v2; \
        (C_)[(ra + 8) * RS + cc + 1] = v3; \
    } \
} while (0)

// depth-2 streamed GEMM (GINE; 2 CTAs/SM hide residual latency)
__device__ __forceinline__ void sgemm64hl(const float* __restrict__ A,
                                          const float* __restrict__ Whl,
                                          const float* __restrict__ bias,
                                          float* __restrict__ C,
                                          float* __restrict__ wbuf,
                                          bool relu, bool accum)
{
    int tid = threadIdx.x;
    int w = tid >> 5;
    int lane = tid & 31;
    int g = lane >> 2;
    int tig = lane & 3;
    int ra = (w & 3) * 16 + g;
    int colBase = (w >> 2) * 64;

    float acc[8][4];
#pragma unroll
    for (int j = 0; j < 8; j++)
#pragma unroll
        for (int q = 0; q < 4; q++) acc[j][q] = 0.0f;

    cp_whl(Whl, wbuf);
    CP_COMMIT();
#pragma unroll
    for (int c = 0; c < 8; c++) {
        if (c < 7) {
            cp_whl(Whl + (c + 1) * 16 * 256, wbuf + ((c + 1) & 1) * 16 * WRS);
            CP_COMMIT();
            CP_WAIT1();
        } else {
            CP_WAIT0();
        }
        __syncthreads();
        const float* Wc = wbuf + (c & 1) * 16 * WRS;
        HL_CHUNK_BODY(A, Wc, c * 16, acc);
        __syncthreads();
    }
    HL_EPILOG(bias, relu, accum, C, acc);
}

// depth-4 streamed GEMM (SAB): ONE barrier per chunk.
// Order per iteration: wait(own groups) -> sync (orders chunk data + frees the
// buffer written next) -> issue chunk c+3 -> compute chunk c. Buffer (c+3)&3 is
// chunk (c-1)'s, whose readers the sync just drained. Entry prefetch of buf 0-2
// is safe because the PREVIOUS GEMM's iteration-7 sync drained readers of those
// buffers (chunks 4,5,6 computed before it). A-operand writes are ordered by
// iteration 0's sync. NO trailing barrier: callers sync before reading C except
// when the next op is another sgemm (its iteration-0 sync covers the epilogue).
__device__ __forceinline__ void sgemm64hl4(const float* __restrict__ A,
                                           const float* __restrict__ Whl,
                                           const float* __restrict__ bias,
                                           float* __restrict__ C,
                                           float* __restrict__ wbuf,
                                           bool relu, bool accum)
{
    int tid = threadIdx.x;
    int w = tid >> 5;
    int lane = tid & 31;
    int g = lane >> 2;
    int tig = lane & 3;
    int ra = (w & 3) * 16 + g;
    int colBase = (w >> 2) * 64;

    float acc[8][4];
#pragma unroll
    for (int j = 0; j < 8; j++)
#pragma unroll
        for (int q = 0; q < 4; q++) acc[j][q] = 0.0f;

    cp_whl(Whl, wbuf);
    CP_COMMIT();
    cp_whl(Whl + 1 * 16 * 256, wbuf + 1 * 16 * WRS);
    CP_COMMIT();
    cp_whl(Whl + 2 * 16 * 256, wbuf + 2 * 16 * WRS);
    CP_COMMIT();
#pragma unroll
    for (int c = 0; c < 8; c++) {
        if (c < 5) {
            CP_WAIT2();             // chunk c complete (c+1, c+2 outstanding)
        } else if (c == 5) {
            CP_WAIT2();
        } else if (c == 6) {
            CP_WAIT1();
        } else {
            CP_WAIT0();
        }
        __syncthreads();            // data visible + buffer (c+3)&3 free
        if (c < 5) {
            cp_whl(Whl + (c + 3) * 16 * 256, wbuf + ((c + 3) & 3) * 16 * WRS);
            CP_COMMIT();
        }
        const float* Wc = wbuf + (c & 3) * 16 * WRS;
        HL_CHUNK_BODY(A, Wc, c * 16, acc);
    }
    HL_EPILOG(bias, relu, accum, C, acc);
}

// ---------------- SIMT variable-K GEMM (input projection, K=74) --------------
#define GEMM_K4(ap0_, ap1_, ap2_, ap3_, Wrow_, accv_) do { \
    ulonglong2 w01_ = *reinterpret_cast<const ulonglong2*>(Wrow_); \
    ulonglong2 w23_ = *reinterpret_cast<const ulonglong2*>((Wrow_) + 4); \
    FFMA2(accv_[0][0], ap0_, w01_.x); FFMA2(accv_[0][1], ap0_, w01_.y); \
    FFMA2(accv_[0][2], ap0_, w23_.x); FFMA2(accv_[0][3], ap0_, w23_.y); \
    FFMA2(accv_[1][0], ap1_, w01_.x); FFMA2(accv_[1][1], ap1_, w01_.y); \
    FFMA2(accv_[1][2], ap1_, w23_.x); FFMA2(accv_[1][3], ap1_, w23_.y); \
    FFMA2(accv_[2][0], ap2_, w01_.x); FFMA2(accv_[2][1], ap2_, w01_.y); \
    FFMA2(accv_[2][2], ap2_, w23_.x); FFMA2(accv_[2][3], ap2_, w23_.y); \
    FFMA2(accv_[3][0], ap3_, w01_.x); FFMA2(accv_[3][1], ap3_, w01_.y); \
    FFMA2(accv_[3][2], ap3_, w23_.x); FFMA2(accv_[3][3], ap3_, w23_.y); \
} while (0)

__device__ __forceinline__ void sgemm_var(const float* __restrict__ A, int lda, int K,
                                          const float* __restrict__ Wg, int gstride,
                                          const float* __restrict__ bias,
                                          float* __restrict__ C,
                                          float* __restrict__ wbuf)
{
    int tid = threadIdx.x;
    int r0 = (tid >> 4) * 4;
    int c0 = (tid & 15) * 8;
    ull acc[4][4];
#pragma unroll
    for (int i = 0; i < 4; i++)
#pragma unroll
        for (int j = 0; j < 4; j++) acc[i][j] = 0ULL;

    int nch = (K + 31) / 32;
    cp_chunk_rows(Wg, gstride, wbuf, K < 32 ? K : 32);
    CP_COMMIT();
    for (int c = 0; c < nch; c++) {
        if (c + 1 < nch) {
            int rows = K - (c + 1) * 32;
            if (rows > 32) rows = 32;
            cp_chunk_rows(Wg + (c + 1) * 32 * gstride, gstride,
                          wbuf + ((c + 1) & 1) * 32 * RS, rows);
            CP_COMMIT();
            CP_WAIT1();
        } else {
            CP_WAIT0();
        }
        __syncthreads();
        const float* Wc = wbuf + (c & 1) * 32 * RS;
        int kbase = c * 32;
        int kn = K - kbase;
        if (kn > 32) kn = 32;
        for (int kk = 0; kk < kn; kk++) {
            ull p0, p1, p2, p3;
            float v0 = A[(r0 + 0) * lda + kbase + kk];
            float v1 = A[(r0 + 1) * lda + kbase + kk];
            float v2 = A[(r0 + 2) * lda + kbase + kk];
            float v3 = A[(r0 + 3) * lda + kbase + kk];
            PACK2(p0, v0); PACK2(p1, v1); PACK2(p2, v2); PACK2(p3, v3);
            GEMM_K4(p0, p1, p2, p3, &Wc[kk * RS + c0], acc);
        }
        __syncthreads();
    }
#pragma unroll
    for (int i = 0; i < 4; i++)
#pragma unroll
        for (int j = 0; j < 4; j++) {
            float lo, hi;
            UNPK2(lo, hi, acc[i][j]);
            lo += bias[c0 + 2 * j];
            hi += bias[c0 + 2 * j + 1];
            C[(r0 + i) * RS + c0 + 2 * j]     = lo;
            C[(r0 + i) * RS + c0 + 2 * j + 1] = hi;
        }
}

// per-row layernorm over 64 rows (8 warps); X,O stride RS
__device__ __forceinline__ void ln_rows(const float* __restrict__ X, float* __restrict__ O,
                                        const float* __restrict__ gg, const float* __restrict__ bb)
{
    int wid = threadIdx.x >> 5;
    int lane = threadIdx.x & 31;
    for (int r = wid; r < SS; r += 8) {
        float v0 = X[r * RS + lane];
        float v1 = X[r * RS + lane + 32];
        float v2 = X[r * RS + lane + 64];
        float v3 = X[r * RS + lane + 96];
        float s = v0 + v1 + v2 + v3;
        float ss = v0 * v0 + v1 * v1 + v2 * v2 + v3 * v3;
#pragma unroll
        for (int o = 16; o; o >>= 1) {
            s += __shfl_xor_sync(0xffffffffu, s, o);
            ss += __shfl_xor_sync(0xffffffffu, ss, o);
        }
        float mu = s * (1.0f / HH);
        float var = ss * (1.0f / HH) - mu * mu;
        float inv = rsqrtf(var + 1e-5f);
        O[r * RS + lane]      = (v0 - mu) * inv * gg[lane]      + bb[lane];
        O[r * RS + lane + 32] = (v1 - mu) * inv * gg[lane + 32] + bb[lane + 32];
        O[r * RS + lane + 64] = (v2 - mu) * inv * gg[lane + 64] + bb[lane + 64];
        O[r * RS + lane + 96] = (v3 - mu) * inv * gg[lane + 96] + bb[lane + 96];
    }
}

// ---------------- prologue: edge hist + weight hi/lo split (fused) -----------
__global__ void edge_hist_whl_kernel(const int* __restrict__ dst,
                                     const float* __restrict__ gW1,
                                     const float* __restrict__ gW2,
                                     const float* __restrict__ Wq,
                                     const float* __restrict__ Wk,
                                     const float* __restrict__ Wv,
                                     const float* __restrict__ Wo,
                                     const float* __restrict__ fW1,
                                     const float* __restrict__ fW2)
{
    int b = blockIdx.x;
    if (b < EE / 256) {
        int e = b * 256 + threadIdx.x;
        atomicAdd(&g_dcnt[dst[e]], 1);      // g_dcnt zero at entry (invariant)
        return;
    }
    int sb = b - EE / 256;
    int s = sb >> 6;
    int i = (sb & 63) * 256 + threadIdx.x;
    int k = i >> 7;
    int j = i & 127;
    const float* srcp;
    if (s < 4) {
        srcp = gW1 + s * 16384 + k * 128 + j;
    } else if (s < 8) {
        srcp = gW2 + (s - 4) * 16384 + k * 128 + j;
    } else {
        int l = (s - 8) / 12;
        int t = (s - 8) % 12;
        if (t < 4) {
            const float* base = (t == 0) ? Wq : (t == 1) ? Wk : (t == 2) ? Wv : Wo;
            srcp = base + l * 16384 + k * 128 + j;
        } else if (t < 8) {
            int c = t - 4;
            srcp = fW1 + l * 65536 + k * 512 + c * 128 + j;
        } else {
            int c = t - 8;
            srcp = fW2 + l * 65536 + (c * 128 + k) * 128 + j;
        }
    }
    float v = *srcp;
    unsigned hi;
    TF32(hi, v);
    float lo = v - __uint_as_float(hi);
    unsigned lou;
    TF32(lou, lo);
    float* dstp = g_whl + s * 32768 + k * 256;
    dstp[j] = __uint_as_float(hi);
    dstp[128 + j] = __uint_as_float(lou);
}

__global__ void dscan_kernel()
{
    __shared__ int sh[64];
    int m = blockIdx.x;
    int t = threadIdx.x;
    int c = g_dcnt[m * 64 + t];
    sh[t] = c;
    __syncthreads();
    for (int off = 1; off < 64; off <<= 1) {
        int v = (t >= off) ? sh[t - off] : 0;
        __syncthreads();
        sh[t] += v;
        __syncthreads();
    }
    g_dstart[m * 65 + t] = sh[t] - c;
    if (t == 63) g_dstart[m * 65 + 64] = sh[63];
    g_dcnt[m * 64 + t] = 0;
    g_dfill[m * 64 + t] = 0;
}

__global__ void edge_scatter_gather_kernel(const int* __restrict__ dst,
                                           const int* __restrict__ src,
                                           const float* __restrict__ ef)
{
    int e = blockIdx.x * blockDim.x + threadIdx.x;
    if (e < EE) {
        int dv = dst[e];
        int p = atomicAdd(&g_dfill[dv], 1);
        int m = dv >> 6;
        int d = dv & 63;
        int slot = m * EPM + g_dstart[m * 65 + d] + p;
        g_efs[slot] = reinterpret_cast<const float4*>(ef)[e];
        g_srcs[slot] = (unsigned char)(src[e] & (SS - 1));
    }
}

// ---------------- GINE layer (1 molecule per CTA, 2 CTAs/SM) -----------------
__global__ void __launch_bounds__(NT, 2) gine_kernel(
                            const float* __restrict__ nf,
                            const float* __restrict__ Win, const float* __restrict__ bin,
                            const float* __restrict__ We, const float* __restrict__ be,
                            int s1, const float* __restrict__ b1,
                            int s2, const float* __restrict__ b2,
                            int mode)
{
    extern __shared__ float smem[];
    float* hb   = smem;                  // 64xRS (h; later reused as z1)
    float* ag   = hb + SS * RS;          // 64xRS (nf / z -> z2)
    float* wbuf = ag + SS * RS;          // 2x32xRS floats
    float* wesm = wbuf + 2 * 32 * RS;    // 4x128
    float* besm = wesm + 4 * HH;         // 128
    int m = blockIdx.x;
    int row0 = m * SS;
    int tid = threadIdx.x;
    const float* W1hl = g_whl + (size_t)s1 * 32768;
    const float* W2hl = g_whl + (size_t)s2 * 32768;

    {
        for (int i = tid; i < 4 * HH; i += NT) wesm[i] = We[i];
        if (tid < HH) besm[tid] = be[tid];
    }
    if (mode == 0) {
        for (int i = tid; i < SS * NF; i += NT) ag[i] = nf[row0 * NF + i];
        sgemm_var(ag, NF, NF, Win, HH, bin, hb, wbuf);
        __syncthreads();
        {
            float4* gh4 = reinterpret_cast<float4*>(g_h + row0 * HH);
            for (int i = tid; i < SS * 32; i += NT) {
                int r = i >> 5, c4 = i & 31;
                gh4[r * 32 + c4] = *reinterpret_cast<const float4*>(&hb[r * RS + c4 * 4]);
            }
        }
    } else {
        float4* gh4 = reinterpret_cast<float4*>(g_h + row0 * HH);
        const float4* gz4 = reinterpret_cast<const float4*>(g_z + row0 * HH);
        for (int i = tid; i < SS * 32; i += NT) {
            int rr = i >> 5, c4 = i & 31;
            int f0 = c4 * 4;
            float4 a = *reinterpret_cast<const float4*>(&g_bn_a[f0]);
            float4 c = *reinterpret_cast<const float4*>(&g_bn_c[f0]);
            float4 z = gz4[i];
            float4 h = gh4[i];
            float4 r;
            r.x = fmaxf(fmaf(z.x, a.x, c.x), 0.f) + h.x;
            r.y = fmaxf(fmaf(z.y, a.y, c.y), 0.f) + h.y;
            r.z = fmaxf(fmaf(z.z, a.z, c.z), 0.f) + h.z;
            r.w = fmaxf(fmaf(z.w, a.w, c.w), 0.f) + h.w;
            *reinterpret_cast<float4*>(&hb[rr * RS + c4 * 4]) = r;
            gh4[i] = r;
        }
    }
    __syncthreads();

    // message passing: 8 warps over 64 dst rows, atomic-free
    {
        int wid = tid >> 5, lane = tid & 31;
        int ebeg = m * EPM;
        const int* gd = g_dstart + m * 65;
        float wr[4][4], br[4];
#pragma unroll
        for (int q = 0; q < 4; q++) {
            int f = lane + 32 * q;
            wr[q][0] = wesm[f];
            wr[q][1] = wesm[HH + f];
            wr[q][2] = wesm[2 * HH + f];
            wr[q][3] = wesm[3 * HH + f];
            br[q] = besm[f];
        }
        for (int d = wid; d < SS; d += 8) {
            float a0 = 0.f, a1 = 0.f, a2 = 0.f, a3 = 0.f;
            int b = gd[d], en = gd[d + 1];
            for (int idx = b; idx < en; idx++) {
                float4 f4 = g_efs[ebeg + idx];
                int s = g_srcs[ebeg + idx];
                const float* hr = &hb[s * RS];
                float m0 = hr[lane]      + f4.x * wr[0][0] + f4.y * wr[0][1] + f4.z * wr[0][2] + f4.w * wr[0][3] + br[0];
                float m1 = hr[lane + 32] + f4.x * wr[1][0] + f4.y * wr[1][1] + f4.z * wr[1][2] + f4.w * wr[1][3] + br[1];
                float m2_ = hr[lane + 64] + f4.x * wr[2][0] + f4.y * wr[2][1] + f4.z * wr[2][2] + f4.w * wr[2][3] + br[2];
                float m3 = hr[lane + 96] + f4.x * wr[3][0] + f4.y * wr[3][1] + f4.z * wr[3][2] + f4.w * wr[3][3] + br[3];
                a0 += fmaxf(m0, 0.f);
                a1 += fmaxf(m1, 0.f);
                a2 += fmaxf(m2_, 0.f);
                a3 += fmaxf(m3, 0.f);
            }
            ag[d * RS + lane]      = a0 + hb[d * RS + lane];
            ag[d * RS + lane + 32] = a1 + hb[d * RS + lane + 32];
            ag[d * RS + lane + 64] = a2 + hb[d * RS + lane + 64];
            ag[d * RS + lane + 96] = a3 + hb[d * RS + lane + 96];
        }
    }
    sgemm64hl(ag, W1hl, b1, hb, wbuf, true, false);    // z1 = relu(z@W1+b1)
    __syncthreads();
    sgemm64hl(hb, W2hl, b2, ag, wbuf, false, false);   // z2 = z1@W2+b2
    __syncthreads();

    {   // BN partial stats
        int f = tid & 127;
        int c = tid >> 7;
        float s = 0.f, ss = 0.f;
        for (int r = c * 32; r < c * 32 + 32; r++) {
            float v = ag[r * RS + f];
            s += v;
            ss += v * v;
        }
        atomicAdd(&g_sum[f], s);
        atomicAdd(&g_sumsq[f], ss);
    }
    {
        float4* gz4 = reinterpret_cast<float4*>(g_z + row0 * HH);
        for (int i = tid; i < SS * 32; i += NT) {
            int r = i >> 5, c4 = i & 31;
            gz4[r * 32 + c4] = *reinterpret_cast<const float4*>(&ag[r * RS + c4 * 4]);
        }
    }
}

__global__ void bn_finalize_kernel(const float* __restrict__ bng, const float* __restrict__ bnb)
{
    int f = threadIdx.x;
    float mu = g_sum[f] * (1.0f / NN);
    float var = g_sumsq[f] * (1.0f / NN) - mu * mu;
    float inv = rsqrtf(var + 1e-5f);
    float a = inv * bng[f];
    g_bn_a[f] = a;
    g_bn_c[f] = bnb[f] - mu * a;
    g_sum[f] = 0.0f;
    g_sumsq[f] = 0.0f;
}

// ---------------- SAB layer (NT=256, depth-4 single-barrier GEMMs) -----------
__global__ void __launch_bounds__(NT) sab_kernel(
                           int sbase,
                           const float* __restrict__ b1, const float* __restrict__ b2,
                           const float* __restrict__ l1g, const float* __restrict__ l1b,
                           const float* __restrict__ l2g, const float* __restrict__ l2b,
                           const int* __restrict__ lengths, float* __restrict__ out,
                           int fuse_bn)
{
    extern __shared__ float smem[];
    float* xb   = smem;                  // 64xRS
    float* qb   = xb + SS * RS;
    float* kb   = qb + SS * RS;
    float* vb   = kb + SS * RS;
    float* wbuf = vb + SS * RS;          // 4x16xWRS floats; aliased as score scratch
    float* scr  = wbuf;                  // 64x65 fits (4160 <= 16896)
    int m = blockIdx.x;
    int row0 = m * SS;
    int tid = threadIdx.x;
    const float* Qhl = g_whl + (size_t)(sbase + 0) * 32768;
    const float* Khl = g_whl + (size_t)(sbase + 1) * 32768;
    const float* Vhl = g_whl + (size_t)(sbase + 2) * 32768;
    const float* Ohl = g_whl + (size_t)(sbase + 3) * 32768;

    {
        const float4* gx4 = reinterpret_cast<const float4*>(g_h + row0 * HH);
        if (fuse_bn) {
            const float4* gz4 = reinterpret_cast<const float4*>(g_z + row0 * HH);
            for (int i = tid; i < SS * 32; i += NT) {
                int rr = i >> 5, c4 = i & 31;
                int f0 = c4 * 4;
                float4 a = *reinterpret_cast<const float4*>(&g_bn_a[f0]);
                float4 c = *reinterpret_cast<const float4*>(&g_bn_c[f0]);
                float4 z = gz4[i];
                float4 h = gx4[i];
                float4 r;
                r.x = fmaxf(fmaf(z.x, a.x, c.x), 0.f) + h.x;
                r.y = fmaxf(fmaf(z.y, a.y, c.y), 0.f) + h.y;
                r.z = fmaxf(fmaf(z.z, a.z, c.z), 0.f) + h.z;
                r.w = fmaxf(fmaf(z.w, a.w, c.w), 0.f) + h.w;
                *reinterpret_cast<float4*>(&xb[rr * RS + c4 * 4]) = r;
            }
        } else {
            for (int i = tid; i < SS * 32; i += NT) {
                int rr = i >> 5, c4 = i & 31;
                *reinterpret_cast<float4*>(&xb[rr * RS + c4 * 4]) = gx4[i];
            }
        }
    }
    __syncthreads();
    ln_rows(xb, vb, l1g, l1b);                 // xn -> vb (temp)
    sgemm64hl4(vb, Qhl, nullptr, qb, wbuf, false, false);   // q = xn @ Wq
    sgemm64hl4(xb, Khl, nullptr, kb, wbuf, false, false);   // k = x @ Wk
    sgemm64hl4(xb, Vhl, nullptr, vb, wbuf, false, false);   // v = x @ Wv
    __syncthreads();

    int len = lengths[m];
    const float scale = 0.25f;
    for (int hh = 0; hh < NH; hh++) {
        {   // scores
            int i = tid >> 2;
            int j0 = (tid & 3) * 16;
            ull q2[8];
            const ull* qrow = reinterpret_cast<const ull*>(&qb[i * RS + hh * DH]);
#pragma unroll
            for (int d2 = 0; d2 < 8; d2++) q2[d2] = qrow[d2];
#pragma unroll
            for (int jj = 0; jj < 16; jj++) {
                int j = j0 + jj;
                const ull* krow = reinterpret_cast<const ull*>(&kb[j * RS + hh * DH]);
                ull s2 = 0ULL;
#pragma unroll
                for (int d2 = 0; d2 < 8; d2++) FFMA2(s2, q2[d2], krow[d2]);
                float lo, hi;
                UNPK2(lo, hi, s2);
                float sdot = lo + hi;
                scr[i * 65 + j] = (i < len && j < len) ? sdot * scale : -CUDART_INF_F;
            }
        }
        __syncthreads();
        {   // softmax rows
            int wid = tid >> 5, lane = tid & 31;
            for (int r = wid; r < SS; r += 8) {
                float x0 = scr[r * 65 + lane];
                float x1 = scr[r * 65 + lane + 32];
                float mx = fmaxf(x0, x1);
#pragma unroll
                for (int o = 16; o; o >>= 1) mx = fmaxf(mx, __shfl_xor_sync(0xffffffffu, mx, o));
                float e0 = (r < len && lane < len)      ? __expf(x0 - mx) : 0.f;
                float e1 = (r < len && lane + 32 < len) ? __expf(x1 - mx) : 0.f;
                float sm = e0 + e1;
#pragma unroll
                for (int o = 16; o; o >>= 1) sm += __shfl_xor_sync(0xffffffffu, sm, o);
                float rinv = (sm > 0.f) ? (1.0f / sm) : 0.f;
                scr[r * 65 + lane]      = e0 * rinv;
                scr[r * 65 + lane + 32] = e1 * rinv;
            }
        }
        __syncthreads();
        {   // att_h = alpha @ v_h, overwrite dead q_h columns
            int i2 = tid >> 2;
            int d0 = (tid & 3) * 4;
            ull acc0 = 0ULL, acc1 = 0ULL;
#pragma unroll 8
            for (int j = 0; j < SS; j++) {
                float al = scr[i2 * 65 + j];
                ull al2;
                PACK2(al2, al);
                const ull* vr = reinterpret_cast<const ull*>(&vb[j * RS + hh * DH + d0]);
                FFMA2(acc0, al2, vr[0]);
                FFMA2(acc1, al2, vr[1]);
            }
            float* qr = &qb[i2 * RS + hh * DH + d0];
            float lo, hi;
            UNPK2(lo, hi, acc0); qr[0] = lo; qr[1] = hi;
            UNPK2(lo, hi, acc1); qr[2] = lo; qr[3] = hi;
        }
        __syncthreads();   // scr reuse next head; last head: orders scr reads
    }                      // before Wo GEMM's entry cp into aliased wbuf

    sgemm64hl4(qb, Ohl, nullptr, xb, wbuf, false, true);    // x += att @ Wo
    __syncthreads();
    ln_rows(xb, kb, l2g, l2b);                              // xn2 -> kb
    for (int c = 0; c < 4; c++) {
        const float* F1hl = g_whl + (size_t)(sbase + 4 + c) * 32768;
        const float* F2hl = g_whl + (size_t)(sbase + 8 + c) * 32768;
        sgemm64hl4(kb, F1hl, b1 + c * HH, qb, wbuf, true, false);
        sgemm64hl4(qb, F2hl, (c == 0) ? b2 : nullptr, xb, wbuf, false, true);
    }
    __syncthreads();

    float* op = out ? out : g_h;
    {
        float4* o4 = reinterpret_cast<float4*>(op + row0 * HH);
        for (int i = tid; i < SS * 32; i += NT) {
            int r = i >> 5, c4 = i & 31;
            o4[r * 32 + c4] = *reinterpret_cast<const float4*>(&xb[r * RS + c4 * 4]);
        }
    }
}

// ---------------- launch ------------------------------------------------------
extern "C" void kernel_launch(void* const* d_in, const int* in_sizes, int n_in,
                              void* d_out, int out_size)
{
    const float* node_feat = (const float*)d_in[0];
    const float* edge_feat = (const float*)d_in[1];
    const float* W_in   = (const float*)d_in[2];
    const float* b_in   = (const float*)d_in[3];
    const float* W_e    = (const float*)d_in[4];
    const float* b_e    = (const float*)d_in[5];
    const float* gW1    = (const float*)d_in[6];
    const float* gb1    = (const float*)d_in[7];
    const float* gW2    = (const float*)d_in[8];
    const float* gb2    = (const float*)d_in[9];
    const float* bn_g   = (const float*)d_in[10];
    const float* bn_b   = (const float*)d_in[11];
    const float* Wq     = (const float*)d_in[12];
    const float* Wk     = (const float*)d_in[13];
    const float* Wv     = (const float*)d_in[14];
    const float* Wo     = (const float*)d_in[15];
    const float* fW1    = (const float*)d_in[16];
    const float* fb1    = (const float*)d_in[17];
    const float* fW2    = (const float*)d_in[18];
    const float* fb2    = (const float*)d_in[19];
    const float* l1g    = (const float*)d_in[20];
    const float* l1b    = (const float*)d_in[21];
    const float* l2g    = (const float*)d_in[22];
    const float* l2b    = (const float*)d_in[23];
    const int*   src    = (const int*)d_in[24];
    const int*   dst    = (const int*)d_in[25];
    const int*   lengths= (const int*)d_in[26];

    const int GINE_SMEM = (2 * SS * RS + 2 * 32 * RS + 4 * HH + HH) * 4;
    const int SAB_SMEM  = (4 * SS * RS + 4 * 16 * WRS) * 4;

    cudaFuncSetAttribute(gine_kernel, cudaFuncAttributeMaxDynamicSharedMemorySize, GINE_SMEM);
    cudaFuncSetAttribute(sab_kernel, cudaFuncAttributeMaxDynamicSharedMemorySize, SAB_SMEM);

    // 3-launch prologue (hist + weight split fused) -> gine at launch index 3
    edge_hist_whl_kernel<<<EE / 256 + 32 * 64, 256>>>(dst, gW1, gW2, Wq, Wk, Wv, Wo, fW1, fW2);
    dscan_kernel<<<BB, 64>>>();
    edge_scatter_gather_kernel<<<EE / 256, 256>>>(dst, src, edge_feat);

    for (int l = 0; l < LG; l++) {
        gine_kernel<<<BB, NT, GINE_SMEM>>>(node_feat, W_in, b_in, W_e, b_e,
                                           l, gb1 + l * HH,
                                           4 + l, gb2 + l * HH,
                                           l == 0 ? 0 : 1);
        bn_finalize_kernel<<<1, HH>>>(bn_g + l * HH, bn_b + l * HH);
    }

    for (int l = 0; l < LSS; l++) {
        sab_kernel<<<BB, NT, SAB_SMEM>>>(8 + l * 12,
                                         fb1 + l * DFF, fb2 + l * HH,
                                         l1g + l * HH, l1b + l * HH,
                                         l2g + l * HH, l2b + l * HH,
                                         lengths,
                                         (l == LSS - 1) ? (float*)d_out : nullptr,
                                         l == 0 ? 1 : 0);
    }
}

// round 16
// speedup vs baseline: 1.0438x; 1.0195x over previous
#include <cuda_runtime.h>
#include <math_constants.h>
#include <cstdint>

#define NN  131072      // nodes = B*S
#define HH  128         // hidden
#define EE  1048576     // edges
#define BB  2048        // molecules
#define SS  64          // nodes per molecule
#define NF  74          // input node features
#define DFF 512         // ffn hidden
#define LG  4           // gine layers
#define LSS 2           // sab layers
#define NH  8           // heads
#define DH  16          // head dim
#define NT  256         // threads per CTA
#define EPM 1024        // edge slots per molecule
#define RS  136         // padded row stride (floats) for 64x128 smem tiles
#define RS4 34          // float4s per padded row
#define WRS 264         // padded row stride for hi|lo weight chunks (8 mod 32)

typedef unsigned long long ull;

#define PACK2(out, a)  asm("mov.b64 %0, {%1, %1};" : "=l"(out) : "r"(__float_as_uint(a)))
#define FFMA2(acc, a, b) asm("fma.rn.f32x2 %0, %1, %2, %0;" : "+l"(acc) : "l"(a), "l"(b))
#define UNPK2(lo, hi, in) do { unsigned _l, _h; \
    asm("mov.b64 {%0, %1}, %2;" : "=r"(_l), "=r"(_h) : "l"(in)); \
    lo = __uint_as_float(_l); hi = __uint_as_float(_h); } while (0)

#define CP_ASYNC16(s, g) asm volatile("cp.async.cg.shared.global [%0], [%1], 16;" \
    :: "r"(s), "l"(g))
#define CP_COMMIT() asm volatile("cp.async.commit_group;" ::: "memory")
#define CP_WAIT0() asm volatile("cp.async.wait_group 0;" ::: "memory")
#define CP_WAIT1() asm volatile("cp.async.wait_group 1;" ::: "memory")
#define CP_WAIT2() asm volatile("cp.async.wait_group 2;" ::: "memory")

#define TF32(o, f_) asm("cvt.rna.tf32.f32 %0, %1;" : "=r"(o) : "f"(f_))
#define MMA_TF32(d, a, b0_, b1_) \
    asm volatile("mma.sync.aligned.m16n8k8.row.col.f32.tf32.tf32.f32 " \
        "{%0,%1,%2,%3},{%4,%5,%6,%7},{%8,%9},{%0,%1,%2,%3};" \
        : "+f"(d[0]), "+f"(d[1]), "+f"(d[2]), "+f"(d[3]) \
        : "r"(a[0]), "r"(a[1]), "r"(a[2]), "r"(a[3]), "r"(b0_), "r"(b1_))

// ---------------- scratch (device globals) -----------------------------------
__device__ __align__(16) float g_h[NN * HH];
__device__ __align__(16) float g_z[NN * HH];
__device__ __align__(16) float g_sum[HH];
__device__ __align__(16) float g_sumsq[HH];
__device__ __align__(16) float g_bn_a[HH];
__device__ __align__(16) float g_bn_c[HH];
__device__ int g_dcnt[NN];
__device__ int g_dfill[NN];
__device__ int g_dstart[BB * 65];
__device__ __align__(16) float4 g_efs[BB * EPM];
__device__ unsigned char g_srcs[BB * EPM];
// pre-split weights: 32 slices, 128 rows x 256 (hi|lo interleaved per column)
__device__ __align__(16) float g_whl[32 * 128 * 256];

// ---------------- weight chunk streaming -------------------------------------
// cp.async a 16-row x 256-col (hi|lo interleaved) chunk into padded smem
__device__ __forceinline__ void cp_whl(const float* __restrict__ g, float* __restrict__ s)
{
    unsigned sa = (unsigned)__cvta_generic_to_shared(s);
#pragma unroll
    for (int u = threadIdx.x; u < 1024; u += NT) {
        int row = u >> 6;       // 0..15
        int c4 = u & 63;        // 0..63
        CP_ASYNC16(sa + (row * (WRS / 4) + c4) * 16, g + row * 256 + c4 * 4);
    }
}

// plain fp32 W chunk (for sgemm_var / input projection)
__device__ __forceinline__ void cp_chunk_rows(const float* __restrict__ g, int gstride,
                                              float* __restrict__ s, int rows)
{
    unsigned sa = (unsigned)__cvta_generic_to_shared(s);
    int lim = rows * 32;
    for (int u = threadIdx.x; u < lim; u += NT) {
        int row = u >> 5;
        int col4 = u & 31;
        CP_ASYNC16(sa + (row * RS4 + col4) * 16, g + row * gstride + col4 * 4);
    }
}

// ---------------- core MMA body for one 16-row chunk (hi|lo interleaved) -----
#define HL_CHUNK_BODY(A_, Wc_, cbase_, acc_) do { \
    _Pragma("unroll") \
    for (int ks = 0; ks < 2; ks++) { \
        int klo = ks * 8; \
        const float* Ar = (A_) + ra * RS + (cbase_) + klo + tig; \
        float a0f = Ar[0]; \
        float a2f = Ar[4]; \
        float a1f = Ar[8 * RS]; \
        float a3f = Ar[8 * RS + 4]; \
        unsigned ah[4], al[4]; \
        TF32(ah[0], a0f); TF32(ah[1], a1f); TF32(ah[2], a2f); TF32(ah[3], a3f); \
        float r0 = a0f - __uint_as_float(ah[0]); \
        float r1 = a1f - __uint_as_float(ah[1]); \
        float r2 = a2f - __uint_as_float(ah[2]); \
        float r3 = a3f - __uint_as_float(ah[3]); \
        TF32(al[0], r0); TF32(al[1], r1); TF32(al[2], r2); TF32(al[3], r3); \
        const float* Wh0 = (Wc_) + (klo + tig) * WRS; \
        const float* Wh1 = (Wc_) + (klo + tig + 4) * WRS; \
        _Pragma("unroll") \
        for (int j = 0; j < 8; j++) { \
            int n0 = colBase + j * 8 + g; \
            float2 p0 = *reinterpret_cast<const float2*>(Wh0 + 2 * n0); \
            float2 p1 = *reinterpret_cast<const float2*>(Wh1 + 2 * n0); \
            unsigned bh0 = __float_as_uint(p0.x); \
            unsigned bl0 = __float_as_uint(p0.y); \
            unsigned bh1 = __float_as_uint(p1.x); \
            unsigned bl1 = __float_as_uint(p1.y); \
            MMA_TF32(acc_[j], ah, bh0, bh1); \
            MMA_TF32(acc_[j], ah, bl0, bl1); \
            MMA_TF32(acc_[j], al, bh0, bh1); \
        } \
    } \
} while (0)

#define HL_EPILOG(bias_, relu_, accum_, C_, acc_) do { \
    _Pragma("unroll") \
    for (int j = 0; j < 8; j++) { \
        int cc = colBase + j * 8 + 2 * tig; \
        float v0 = acc_[j][0], v1 = acc_[j][1], v2 = acc_[j][2], v3 = acc_[j][3]; \
        if (bias_) { \
            float bA = (bias_)[cc], bB = (bias_)[cc + 1]; \
            v0 += bA; v1 += bB; v2 += bA; v3 += bB; \
        } \
        if (relu_) { \
            v0 = fmaxf(v0, 0.f); v1 = fmaxf(v1, 0.f); \
            v2 = fmaxf(v2, 0.f); v3 = fmaxf(v3, 0.f); \
        } \
        if (accum_) { \
            v0 += (C_)[ra * RS + cc]; \
            v1 += (C_)[ra * RS + cc + 1]; \
            v2 += (C_)[(ra + 8) * RS + cc]; \
            v3 += (C_)[(ra + 8) * RS + cc + 1]; \
        } \
        (C_)[ra * RS + cc]           = v0; \
        (C_)[ra * RS + cc + 1]       = v1; \
        (C_)[(ra + 8) * RS + cc]     = v2; \
        (C_)[(ra + 8) * RS + cc + 1] = v3; \
    } \
} while (0)

// depth-2 streamed GEMM (GINE; 2 CTAs/SM hide residual latency)
__device__ __forceinline__ void sgemm64hl(const float* __restrict__ A,
                                          const float* __restrict__ Whl,
                                          const float* __restrict__ bias,
                                          float* __restrict__ C,
                                          float* __restrict__ wbuf,
                                          bool relu, bool accum)
{
    int tid = threadIdx.x;
    int w = tid >> 5;
    int lane = tid & 31;
    int g = lane >> 2;
    int tig = lane & 3;
    int ra = (w & 3) * 16 + g;
    int colBase = (w >> 2) * 64;

    float acc[8][4];
#pragma unroll
    for (int j = 0; j < 8; j++)
#pragma unroll
        for (int q = 0; q < 4; q++) acc[j][q] = 0.0f;

    cp_whl(Whl, wbuf);
    CP_COMMIT();
#pragma unroll
    for (int c = 0; c < 8; c++) {
        if (c < 7) {
            cp_whl(Whl + (c + 1) * 16 * 256, wbuf + ((c + 1) & 1) * 16 * WRS);
            CP_COMMIT();
            CP_WAIT1();
        } else {
            CP_WAIT0();
        }
        __syncthreads();
        const float* Wc = wbuf + (c & 1) * 16 * WRS;
        HL_CHUNK_BODY(A, Wc, c * 16, acc);
        __syncthreads();
    }
    HL_EPILOG(bias, relu, accum, C, acc);
}

// depth-4 streamed GEMM (SAB): one barrier per chunk (see R15 proof).
__device__ __forceinline__ void sgemm64hl4(const float* __restrict__ A,
                                           const float* __restrict__ Whl,
                                           const float* __restrict__ bias,
                                           float* __restrict__ C,
                                           float* __restrict__ wbuf,
                                           bool relu, bool accum)
{
    int tid = threadIdx.x;
    int w = tid >> 5;
    int lane = tid & 31;
    int g = lane >> 2;
    int tig = lane & 3;
    int ra = (w & 3) * 16 + g;
    int colBase = (w >> 2) * 64;

    float acc[8][4];
#pragma unroll
    for (int j = 0; j < 8; j++)
#pragma unroll
        for (int q = 0; q < 4; q++) acc[j][q] = 0.0f;

    cp_whl(Whl, wbuf);
    CP_COMMIT();
    cp_whl(Whl + 1 * 16 * 256, wbuf + 1 * 16 * WRS);
    CP_COMMIT();
    cp_whl(Whl + 2 * 16 * 256, wbuf + 2 * 16 * WRS);
    CP_COMMIT();
#pragma unroll
    for (int c = 0; c < 8; c++) {
        if (c <= 5) {
            CP_WAIT2();
        } else if (c == 6) {
            CP_WAIT1();
        } else {
            CP_WAIT0();
        }
        __syncthreads();            // data visible + buffer (c+3)&3 free
        if (c < 5) {
            cp_whl(Whl + (c + 3) * 16 * 256, wbuf + ((c + 3) & 3) * 16 * WRS);
            CP_COMMIT();
        }
        const float* Wc = wbuf + (c & 3) * 16 * WRS;
        HL_CHUNK_BODY(A, Wc, c * 16, acc);
    }
    HL_EPILOG(bias, relu, accum, C, acc);
}

// ---------------- SIMT variable-K GEMM (input projection, K=74) --------------
#define GEMM_K4(ap0_, ap1_, ap2_, ap3_, Wrow_, accv_) do { \
    ulonglong2 w01_ = *reinterpret_cast<const ulonglong2*>(Wrow_); \
    ulonglong2 w23_ = *reinterpret_cast<const ulonglong2*>((Wrow_) + 4); \
    FFMA2(accv_[0][0], ap0_, w01_.x); FFMA2(accv_[0][1], ap0_, w01_.y); \
    FFMA2(accv_[0][2], ap0_, w23_.x); FFMA2(accv_[0][3], ap0_, w23_.y); \
    FFMA2(accv_[1][0], ap1_, w01_.x); FFMA2(accv_[1][1], ap1_, w01_.y); \
    FFMA2(accv_[1][2], ap1_, w23_.x); FFMA2(accv_[1][3], ap1_, w23_.y); \
    FFMA2(accv_[2][0], ap2_, w01_.x); FFMA2(accv_[2][1], ap2_, w01_.y); \
    FFMA2(accv_[2][2], ap2_, w23_.x); FFMA2(accv_[2][3], ap2_, w23_.y); \
    FFMA2(accv_[3][0], ap3_, w01_.x); FFMA2(accv_[3][1], ap3_, w01_.y); \
    FFMA2(accv_[3][2], ap3_, w23_.x); FFMA2(accv_[3][3], ap3_, w23_.y); \
} while (0)

__device__ __forceinline__ void sgemm_var(const float* __restrict__ A, int lda, int K,
                                          const float* __restrict__ Wg, int gstride,
                                          const float* __restrict__ bias,
                                          float* __restrict__ C,
                                          float* __restrict__ wbuf)
{
    int tid = threadIdx.x;
    int r0 = (tid >> 4) * 4;
    int c0 = (tid & 15) * 8;
    ull acc[4][4];
#pragma unroll
    for (int i = 0; i < 4; i++)
#pragma unroll
        for (int j = 0; j < 4; j++) acc[i][j] = 0ULL;

    int nch = (K + 31) / 32;
    cp_chunk_rows(Wg, gstride, wbuf, K < 32 ? K : 32);
    CP_COMMIT();
    for (int c = 0; c < nch; c++) {
        if (c + 1 < nch) {
            int rows = K - (c + 1) * 32;
            if (rows > 32) rows = 32;
            cp_chunk_rows(Wg + (c + 1) * 32 * gstride, gstride,
                          wbuf + ((c + 1) & 1) * 32 * RS, rows);
            CP_COMMIT();
            CP_WAIT1();
        } else {
            CP_WAIT0();
        }
        __syncthreads();
        const float* Wc = wbuf + (c & 1) * 32 * RS;
        int kbase = c * 32;
        int kn = K - kbase;
        if (kn > 32) kn = 32;
        for (int kk = 0; kk < kn; kk++) {
            ull p0, p1, p2, p3;
            float v0 = A[(r0 + 0) * lda + kbase + kk];
            float v1 = A[(r0 + 1) * lda + kbase + kk];
            float v2 = A[(r0 + 2) * lda + kbase + kk];
            float v3 = A[(r0 + 3) * lda + kbase + kk];
            PACK2(p0, v0); PACK2(p1, v1); PACK2(p2, v2); PACK2(p3, v3);
            GEMM_K4(p0, p1, p2, p3, &Wc[kk * RS + c0], acc);
        }
        __syncthreads();
    }
#pragma unroll
    for (int i = 0; i < 4; i++)
#pragma unroll
        for (int j = 0; j < 4; j++) {
            float lo, hi;
            UNPK2(lo, hi, acc[i][j]);
            lo += bias[c0 + 2 * j];
            hi += bias[c0 + 2 * j + 1];
            C[(r0 + i) * RS + c0 + 2 * j]     = lo;
            C[(r0 + i) * RS + c0 + 2 * j + 1] = hi;
        }
}

// per-row layernorm over 64 rows (8 warps); X,O stride RS
__device__ __forceinline__ void ln_rows(const float* __restrict__ X, float* __restrict__ O,
                                        const float* __restrict__ gg, const float* __restrict__ bb)
{
    int wid = threadIdx.x >> 5;
    int lane = threadIdx.x & 31;
    for (int r = wid; r < SS; r += 8) {
        float v0 = X[r * RS + lane];
        float v1 = X[r * RS + lane + 32];
        float v2 = X[r * RS + lane + 64];
        float v3 = X[r * RS + lane + 96];
        float s = v0 + v1 + v2 + v3;
        float ss = v0 * v0 + v1 * v1 + v2 * v2 + v3 * v3;
#pragma unroll
        for (int o = 16; o; o >>= 1) {
            s += __shfl_xor_sync(0xffffffffu, s, o);
            ss += __shfl_xor_sync(0xffffffffu, ss, o);
        }
        float mu = s * (1.0f / HH);
        float var = ss * (1.0f / HH) - mu * mu;
        float inv = rsqrtf(var + 1e-5f);
        O[r * RS + lane]      = (v0 - mu) * inv * gg[lane]      + bb[lane];
        O[r * RS + lane + 32] = (v1 - mu) * inv * gg[lane + 32] + bb[lane + 32];
        O[r * RS + lane + 64] = (v2 - mu) * inv * gg[lane + 64] + bb[lane + 64];
        O[r * RS + lane + 96] = (v3 - mu) * inv * gg[lane + 96] + bb[lane + 96];
    }
}

// ---------------- prologue: edge hist + weight hi/lo split (fused) -----------
__global__ void edge_hist_whl_kernel(const int* __restrict__ dst,
                                     const float* __restrict__ gW1,
                                     const float* __restrict__ gW2,
                                     const float* __restrict__ Wq,
                                     const float* __restrict__ Wk,
                                     const float* __restrict__ Wv,
                                     const float* __restrict__ Wo,
                                     const float* __restrict__ fW1,
                                     const float* __restrict__ fW2)
{
    int b = blockIdx.x;
    if (b < EE / 256) {
        int e = b * 256 + threadIdx.x;
        atomicAdd(&g_dcnt[dst[e]], 1);      // g_dcnt zero at entry (invariant)
        return;
    }
    int sb = b - EE / 256;
    int s = sb >> 6;
    int i = (sb & 63) * 256 + threadIdx.x;
    int k = i >> 7;
    int j = i & 127;
    const float* srcp;
    if (s < 4) {
        srcp = gW1 + s * 16384 + k * 128 + j;
    } else if (s < 8) {
        srcp = gW2 + (s - 4) * 16384 + k * 128 + j;
    } else {
        int l = (s - 8) / 12;
        int t = (s - 8) % 12;
        if (t < 4) {
            const float* base = (t == 0) ? Wq : (t == 1) ? Wk : (t == 2) ? Wv : Wo;
            srcp = base + l * 16384 + k * 128 + j;
        } else if (t < 8) {
            int c = t - 4;
            srcp = fW1 + l * 65536 + k * 512 + c * 128 + j;
        } else {
            int c = t - 8;
            srcp = fW2 + l * 65536 + (c * 128 + k) * 128 + j;
        }
    }
    float v = *srcp;
    unsigned hi;
    TF32(hi, v);
    float lo = v - __uint_as_float(hi);
    unsigned lou;
    TF32(lou, lo);
    float* dstp = g_whl + s * 32768 + k * 256;
    dstp[2 * j]     = __uint_as_float(hi);   // interleaved hi|lo
    dstp[2 * j + 1] = __uint_as_float(lou);
}

__global__ void dscan_kernel()
{
    __shared__ int sh[64];
    int m = blockIdx.x;
    int t = threadIdx.x;
    int c = g_dcnt[m * 64 + t];
    sh[t] = c;
    __syncthreads();
    for (int off = 1; off < 64; off <<= 1) {
        int v = (t >= off) ? sh[t - off] : 0;
        __syncthreads();
        sh[t] += v;
        __syncthreads();
    }
    g_dstart[m * 65 + t] = sh[t] - c;
    if (t == 63) g_dstart[m * 65 + 64] = sh[63];
    g_dcnt[m * 64 + t] = 0;
    g_dfill[m * 64 + t] = 0;
}

__global__ void edge_scatter_gather_kernel(const int* __restrict__ dst,
                                           const int* __restrict__ src,
                                           const float* __restrict__ ef)
{
    int e = blockIdx.x * blockDim.x + threadIdx.x;
    if (e < EE) {
        int dv = dst[e];
        int p = atomicAdd(&g_dfill[dv], 1);
        int m = dv >> 6;
        int d = dv & 63;
        int slot = m * EPM + g_dstart[m * 65 + d] + p;
        g_efs[slot] = reinterpret_cast<const float4*>(ef)[e];
        g_srcs[slot] = (unsigned char)(src[e] & (SS - 1));
    }
}

// ---------------- GINE layer (1 molecule per CTA, 2 CTAs/SM) -----------------
__global__ void __launch_bounds__(NT, 2) gine_kernel(
                            const float* __restrict__ nf,
                            const float* __restrict__ Win, const float* __restrict__ bin,
                            const float* __restrict__ We, const float* __restrict__ be,
                            int s1, const float* __restrict__ b1,
                            int s2, const float* __restrict__ b2,
                            int mode)
{
    extern __shared__ float smem[];
    float* hb   = smem;                  // 64xRS (h; later reused as z1)
    float* ag   = hb + SS * RS;          // 64xRS (nf / z -> z2)
    float* wbuf = ag + SS * RS;          // 2x32xRS floats
    float* wesm = wbuf + 2 * 32 * RS;    // 4x128
    float* besm = wesm + 4 * HH;         // 128
    int m = blockIdx.x;
    int row0 = m * SS;
    int tid = threadIdx.x;
    const float* W1hl = g_whl + (size_t)s1 * 32768;
    const float* W2hl = g_whl + (size_t)s2 * 32768;

    {
        for (int i = tid; i < 4 * HH; i += NT) wesm[i] = We[i];
        if (tid < HH) besm[tid] = be[tid];
    }
    if (mode == 0) {
        for (int i = tid; i < SS * NF; i += NT) ag[i] = nf[row0 * NF + i];
        sgemm_var(ag, NF, NF, Win, HH, bin, hb, wbuf);
        __syncthreads();
        {
            float4* gh4 = reinterpret_cast<float4*>(g_h + row0 * HH);
            for (int i = tid; i < SS * 32; i += NT) {
                int r = i >> 5, c4 = i & 31;
                gh4[r * 32 + c4] = *reinterpret_cast<const float4*>(&hb[r * RS + c4 * 4]);
            }
        }
    } else {
        float4* gh4 = reinterpret_cast<float4*>(g_h + row0 * HH);
        const float4* gz4 = reinterpret_cast<const float4*>(g_z + row0 * HH);
        for (int i = tid; i < SS * 32; i += NT) {
            int rr = i >> 5, c4 = i & 31;
            int f0 = c4 * 4;
            float4 a = *reinterpret_cast<const float4*>(&g_bn_a[f0]);
            float4 c = *reinterpret_cast<const float4*>(&g_bn_c[f0]);
            float4 z = gz4[i];
            float4 h = gh4[i];
            float4 r;
            r.x = fmaxf(fmaf(z.x, a.x, c.x), 0.f) + h.x;
            r.y = fmaxf(fmaf(z.y, a.y, c.y), 0.f) + h.y;
            r.z = fmaxf(fmaf(z.z, a.z, c.z), 0.f) + h.z;
            r.w = fmaxf(fmaf(z.w, a.w, c.w), 0.f) + h.w;
            *reinterpret_cast<float4*>(&hb[rr * RS + c4 * 4]) = r;
            gh4[i] = r;
        }
    }
    __syncthreads();

    // message passing: 8 warps over 64 dst rows, atomic-free
    {
        int wid = tid >> 5, lane = tid & 31;
        int ebeg = m * EPM;
        const int* gd = g_dstart + m * 65;
        float wr[4][4], br[4];
#pragma unroll
        for (int q = 0; q < 4; q++) {
            int f = lane + 32 * q;
            wr[q][0] = wesm[f];
            wr[q][1] = wesm[HH + f];
            wr[q][2] = wesm[2 * HH + f];
            wr[q][3] = wesm[3 * HH + f];
            br[q] = besm[f];
        }
        for (int d = wid; d < SS; d += 8) {
            float a0 = 0.f, a1 = 0.f, a2 = 0.f, a3 = 0.f;
            int b = gd[d], en = gd[d + 1];
            for (int idx = b; idx < en; idx++) {
                float4 f4 = g_efs[ebeg + idx];
                int s = g_srcs[ebeg + idx];
                const float* hr = &hb[s * RS];
                float m0 = hr[lane]      + f4.x * wr[0][0] + f4.y * wr[0][1] + f4.z * wr[0][2] + f4.w * wr[0][3] + br[0];
                float m1 = hr[lane + 32] + f4.x * wr[1][0] + f4.y * wr[1][1] + f4.z * wr[1][2] + f4.w * wr[1][3] + br[1];
                float m2_ = hr[lane + 64] + f4.x * wr[2][0] + f4.y * wr[2][1] + f4.z * wr[2][2] + f4.w * wr[2][3] + br[2];
                float m3 = hr[lane + 96] + f4.x * wr[3][0] + f4.y * wr[3][1] + f4.z * wr[3][2] + f4.w * wr[3][3] + br[3];
                a0 += fmaxf(m0, 0.f);
                a1 += fmaxf(m1, 0.f);
                a2 += fmaxf(m2_, 0.f);
                a3 += fmaxf(m3, 0.f);
            }
            ag[d * RS + lane]      = a0 + hb[d * RS + lane];
            ag[d * RS + lane + 32] = a1 + hb[d * RS + lane + 32];
            ag[d * RS + lane + 64] = a2 + hb[d * RS + lane + 64];
            ag[d * RS + lane + 96] = a3 + hb[d * RS + lane + 96];
        }
    }
    sgemm64hl(ag, W1hl, b1, hb, wbuf, true, false);    // z1 = relu(z@W1+b1)
    __syncthreads();
    sgemm64hl(hb, W2hl, b2, ag, wbuf, false, false);   // z2 = z1@W2+b2
    __syncthreads();

    {   // BN partial stats
        int f = tid & 127;
        int c = tid >> 7;
        float s = 0.f, ss = 0.f;
        for (int r = c * 32; r < c * 32 + 32; r++) {
            float v = ag[r * RS + f];
            s += v;
            ss += v * v;
        }
        atomicAdd(&g_sum[f], s);
        atomicAdd(&g_sumsq[f], ss);
    }
    {
        float4* gz4 = reinterpret_cast<float4*>(g_z + row0 * HH);
        for (int i = tid; i < SS * 32; i += NT) {
            int r = i >> 5, c4 = i & 31;
            gz4[r * 32 + c4] = *reinterpret_cast<const float4*>(&ag[r * RS + c4 * 4]);
        }
    }
}

__global__ void bn_finalize_kernel(const float* __restrict__ bng, const float* __restrict__ bnb)
{
    int f = threadIdx.x;
    float mu = g_sum[f] * (1.0f / NN);
    float var = g_sumsq[f] * (1.0f / NN) - mu * mu;
    float inv = rsqrtf(var + 1e-5f);
    float a = inv * bng[f];
    g_bn_a[f] = a;
    g_bn_c[f] = bnb[f] - mu * a;
    g_sum[f] = 0.0f;
    g_sumsq[f] = 0.0f;
}

// ---------------- SAB layer (NT=256, barrier-free attention) -----------------
__global__ void __launch_bounds__(NT) sab_kernel(
                           int sbase,
                           const float* __restrict__ b1, const float* __restrict__ b2,
                           const float* __restrict__ l1g, const float* __restrict__ l1b,
                           const float* __restrict__ l2g, const float* __restrict__ l2b,
                           const int* __restrict__ lengths, float* __restrict__ out,
                           int fuse_bn)
{
    extern __shared__ float smem[];
    float* xb   = smem;                  // 64xRS
    float* qb   = xb + SS * RS;
    float* kb   = qb + SS * RS;
    float* vb   = kb + SS * RS;
    float* wbuf = vb + SS * RS;          // 4x16xWRS floats; aliased as score scratch
    float* scr  = wbuf;                  // 64x65 fits (4160 <= 16896)
    int m = blockIdx.x;
    int row0 = m * SS;
    int tid = threadIdx.x;
    const float* Qhl = g_whl + (size_t)(sbase + 0) * 32768;
    const float* Khl = g_whl + (size_t)(sbase + 1) * 32768;
    const float* Vhl = g_whl + (size_t)(sbase + 2) * 32768;
    const float* Ohl = g_whl + (size_t)(sbase + 3) * 32768;

    {
        const float4* gx4 = reinterpret_cast<const float4*>(g_h + row0 * HH);
        if (fuse_bn) {
            const float4* gz4 = reinterpret_cast<const float4*>(g_z + row0 * HH);
            for (int i = tid; i < SS * 32; i += NT) {
                int rr = i >> 5, c4 = i & 31;
                int f0 = c4 * 4;
                float4 a = *reinterpret_cast<const float4*>(&g_bn_a[f0]);
                float4 c = *reinterpret_cast<const float4*>(&g_bn_c[f0]);
                float4 z = gz4[i];
                float4 h = gx4[i];
                float4 r;
                r.x = fmaxf(fmaf(z.x, a.x, c.x), 0.f) + h.x;
                r.y = fmaxf(fmaf(z.y, a.y, c.y), 0.f) + h.y;
                r.z = fmaxf(fmaf(z.z, a.z, c.z), 0.f) + h.z;
                r.w = fmaxf(fmaf(z.w, a.w, c.w), 0.f) + h.w;
                *reinterpret_cast<float4*>(&xb[rr * RS + c4 * 4]) = r;
            }
        } else {
            for (int i = tid; i < SS * 32; i += NT) {
                int rr = i >> 5, c4 = i & 31;
                *reinterpret_cast<float4*>(&xb[rr * RS + c4 * 4]) = gx4[i];
            }
        }
    }
    __syncthreads();
    ln_rows(xb, vb, l1g, l1b);                 // xn -> vb (temp)
    sgemm64hl4(vb, Qhl, nullptr, qb, wbuf, false, false);   // q = xn @ Wq
    sgemm64hl4(xb, Khl, nullptr, kb, wbuf, false, false);   // k = x @ Wk
    sgemm64hl4(xb, Vhl, nullptr, vb, wbuf, false, false);   // v = x @ Wv
    __syncthreads();   // q/k/v visible to all; also orders scr (aliased wbuf)

    // -------- attention: row i owned by lanes 4i..4i+3 -> warp-local only ----
    {
        int len = lengths[m];
        const float scale = 0.25f;
        int i = tid >> 2;          // row 0..63 (warp w owns rows 8w..8w+7)
        int sub = tid & 3;
        int j0 = sub * 16;
        bool irow = (i < len);
        for (int hh = 0; hh < NH; hh++) {
            // scores for row i, columns j0..j0+15 (registers)
            float sc[16];
            ull q2[8];
            const ull* qrow = reinterpret_cast<const ull*>(&qb[i * RS + hh * DH]);
#pragma unroll
            for (int d2 = 0; d2 < 8; d2++) q2[d2] = qrow[d2];
#pragma unroll
            for (int jj = 0; jj < 16; jj++) {
                int j = j0 + jj;
                const ull* krow = reinterpret_cast<const ull*>(&kb[j * RS + hh * DH]);
                ull s2 = 0ULL;
#pragma unroll
                for (int d2 = 0; d2 < 8; d2++) FFMA2(s2, q2[d2], krow[d2]);
                float lo, hi;
                UNPK2(lo, hi, s2);
                sc[jj] = (irow && j < len) ? (lo + hi) * scale : -CUDART_INF_F;
            }
            // softmax across the 4-lane group (shfl_xor 1, 2 stay in group)
            float mx = sc[0];
#pragma unroll
            for (int jj = 1; jj < 16; jj++) mx = fmaxf(mx, sc[jj]);
            mx = fmaxf(mx, __shfl_xor_sync(0xffffffffu, mx, 1));
            mx = fmaxf(mx, __shfl_xor_sync(0xffffffffu, mx, 2));
            float sm = 0.f;
#pragma unroll
            for (int jj = 0; jj < 16; jj++) {
                float e = (irow && (j0 + jj) < len) ? __expf(sc[jj] - mx) : 0.f;
                sc[jj] = e;
                sm += e;
            }
            sm += __shfl_xor_sync(0xffffffffu, sm, 1);
            sm += __shfl_xor_sync(0xffffffffu, sm, 2);
            float rinv = (irow && sm > 0.f) ? (1.0f / sm) : 0.f;
#pragma unroll
            for (int jj = 0; jj < 16; jj++) scr[i * 65 + j0 + jj] = sc[jj] * rinv;
            __syncwarp();
            // att_h = alpha @ v_h, overwrite dead q_h columns of row i
            {
                int d0 = sub * 4;
                ull acc0 = 0ULL, acc1 = 0ULL;
#pragma unroll 8
                for (int j = 0; j < SS; j++) {
                    float al = scr[i * 65 + j];
                    ull al2;
                    PACK2(al2, al);
                    const ull* vr = reinterpret_cast<const ull*>(&vb[j * RS + hh * DH + d0]);
                    FFMA2(acc0, al2, vr[0]);
                    FFMA2(acc1, al2, vr[1]);
                }
                float* qr = &qb[i * RS + hh * DH + d0];
                float lo, hi;
                UNPK2(lo, hi, acc0); qr[0] = lo; qr[1] = hi;
                UNPK2(lo, hi, acc1); qr[2] = lo; qr[3] = hi;
            }
            __syncwarp();   // qb row i + scr row i settled before next head
        }
    }
    __syncthreads();   // all qb rows + scr (aliased wbuf) before Wo GEMM

    sgemm64hl4(qb, Ohl, nullptr, xb, wbuf, false, true);    // x += att @ Wo
    __syncthreads();
    ln_rows(xb, kb, l2g, l2b);                              // xn2 -> kb
    for (int c = 0; c < 4; c++) {
        const float* F1hl = g_whl + (size_t)(sbase + 4 + c) * 32768;
        const float* F2hl = g_whl + (size_t)(sbase + 8 + c) * 32768;
        sgemm64hl4(kb, F1hl, b1 + c * HH, qb, wbuf, true, false);
        sgemm64hl4(qb, F2hl, (c == 0) ? b2 : nullptr, xb, wbuf, false, true);
    }
    __syncthreads();

    float* op = out ? out : g_h;
    {
        float4* o4 = reinterpret_cast<float4*>(op + row0 * HH);
        for (int i = tid; i < SS * 32; i += NT) {
            int r = i >> 5, c4 = i & 31;
            o4[r * 32 + c4] = *reinterpret_cast<const float4*>(&xb[r * RS + c4 * 4]);
        }
    }
}

// ---------------- launch ------------------------------------------------------
extern "C" void kernel_launch(void* const* d_in, const int* in_sizes, int n_in,
                              void* d_out, int out_size)
{
    const float* node_feat = (const float*)d_in[0];
    const float* edge_feat = (const float*)d_in[1];
    const float* W_in   = (const float*)d_in[2];
    const float* b_in   = (const float*)d_in[3];
    const float* W_e    = (const float*)d_in[4];
    const float* b_e    = (const float*)d_in[5];
    const float* gW1    = (const float*)d_in[6];
    const float* gb1    = (const float*)d_in[7];
    const float* gW2    = (const float*)d_in[8];
    const float* gb2    = (const float*)d_in[9];
    const float* bn_g   = (const float*)d_in[10];
    const float* bn_b   = (const float*)d_in[11];
    const float* Wq     = (const float*)d_in[12];
    const float* Wk     = (const float*)d_in[13];
    const float* Wv     = (const float*)d_in[14];
    const float* Wo     = (const float*)d_in[15];
    const float* fW1    = (const float*)d_in[16];
    const float* fb1    = (const float*)d_in[17];
    const float* fW2    = (const float*)d_in[18];
    const float* fb2    = (const float*)d_in[19];
    const float* l1g    = (const float*)d_in[20];
    const float* l1b    = (const float*)d_in[21];
    const float* l2g    = (const float*)d_in[22];
    const float* l2b    = (const float*)d_in[23];
    const int*   src    = (const int*)d_in[24];
    const int*   dst    = (const int*)d_in[25];
    const int*   lengths= (const int*)d_in[26];

    const int GINE_SMEM = (2 * SS * RS + 2 * 32 * RS + 4 * HH + HH) * 4;
    const int SAB_SMEM  = (4 * SS * RS + 4 * 16 * WRS) * 4;

    cudaFuncSetAttribute(gine_kernel, cudaFuncAttributeMaxDynamicSharedMemorySize, GINE_SMEM);
    cudaFuncSetAttribute(sab_kernel, cudaFuncAttributeMaxDynamicSharedMemorySize, SAB_SMEM);

    // 3-launch prologue (hist + weight split fused) -> gine at launch index 3
    edge_hist_whl_kernel<<<EE / 256 + 32 * 64, 256>>>(dst, gW1, gW2, Wq, Wk, Wv, Wo, fW1, fW2);
    dscan_kernel<<<BB, 64>>>();
    edge_scatter_gather_kernel<<<EE / 256, 256>>>(dst, src, edge_feat);

    for (int l = 0; l < LG; l++) {
        gine_kernel<<<BB, NT, GINE_SMEM>>>(node_feat, W_in, b_in, W_e, b_e,
                                           l, gb1 + l * HH,
                                           4 + l, gb2 + l * HH,
                                           l == 0 ? 0 : 1);
        bn_finalize_kernel<<<1, HH>>>(bn_g + l * HH, bn_b + l * HH);
    }

    for (int l = 0; l < LSS; l++) {
        sab_kernel<<<BB, NT, SAB_SMEM>>>(8 + l * 12,
                                         fb1 + l * DFF, fb2 + l * HH,
                                         l1g + l * HH, l1b + l * HH,
                                         l2g + l * HH, l2b + l * HH,
                                         lengths,
                                         (l == LSS - 1) ? (float*)d_out : nullptr,
                                         l == 0 ? 1 : 0);
    }
}